// round 1
// baseline (speedup 1.0000x reference)
#include <cuda_runtime.h>
#include <math.h>

#define HIDDEN   1024
#define HEADS    16
#define HEAD_DIM 64
#define BATCH    2
#define SEQ      2048
#define MROWS    (BATCH*SEQ)     // 4096
#define KKEEP    1024            // max(1, int(S * (1 - 0.5)))

// ---------------------------------------------------------------------------
// Scratch (device globals; no runtime allocation allowed)
// ---------------------------------------------------------------------------
__device__ float g_Q[(size_t)BATCH*HEADS*SEQ*HEAD_DIM];   // [b,h,s,d] 16MB
__device__ float g_K[(size_t)BATCH*HEADS*SEQ*HEAD_DIM];
__device__ float g_V[(size_t)BATCH*HEADS*SEQ*HEAD_DIM];
__device__ float g_O[(size_t)MROWS*HIDDEN];               // [b,s,hidden] 16MB

// ---------------------------------------------------------------------------
// 64x64x16 fp32 GEMM-NT tile:  C[row,col] = sum_k A[row,k] * W[col,k]
// block = 256 threads, each thread accumulates a 4x4 micro-tile.
// ---------------------------------------------------------------------------
__device__ __forceinline__ void sgemm64_nt(const float* __restrict__ A,
                                           const float* __restrict__ W,
                                           float c[4][4])
{
    __shared__ float As[16][64];
    __shared__ float Bs[16][64];

    const int tid = threadIdx.x;
    const int lr  = tid >> 2;          // 0..63 : tile row loaded by this thread
    const int lc  = (tid & 3) << 2;    // 0,4,8,12 : k-offset (float4)
    const int tx  = tid & 15;
    const int ty  = tid >> 4;
    const int row0 = blockIdx.y * 64;
    const int col0 = blockIdx.x * 64;

    for (int k0 = 0; k0 < HIDDEN; k0 += 16) {
        float4 av = *(const float4*)(A + (size_t)(row0 + lr) * HIDDEN + k0 + lc);
        float4 bv = *(const float4*)(W + (size_t)(col0 + lr) * HIDDEN + k0 + lc);
        As[lc + 0][lr] = av.x; As[lc + 1][lr] = av.y;
        As[lc + 2][lr] = av.z; As[lc + 3][lr] = av.w;
        Bs[lc + 0][lr] = bv.x; Bs[lc + 1][lr] = bv.y;
        Bs[lc + 2][lr] = bv.z; Bs[lc + 3][lr] = bv.w;
        __syncthreads();

        #pragma unroll
        for (int kk = 0; kk < 16; ++kk) {
            float a[4], b[4];
            #pragma unroll
            for (int i = 0; i < 4; ++i) a[i] = As[kk][(ty << 2) + i];
            #pragma unroll
            for (int j = 0; j < 4; ++j) b[j] = Bs[kk][(tx << 2) + j];
            #pragma unroll
            for (int i = 0; i < 4; ++i)
                #pragma unroll
                for (int j = 0; j < 4; ++j)
                    c[i][j] = fmaf(a[i], b[j], c[i][j]);
        }
        __syncthreads();
    }
}

// QKV projections: out column j -> head h=j/64, dim d=j%64; row -> (b,s).
// Writes Q/K/V in [b,h,s,d] layout. grid.z selects which projection.
__global__ void qkv_gemm_kernel(const float* __restrict__ x,
                                const float* __restrict__ Wq,
                                const float* __restrict__ Wk,
                                const float* __restrict__ Wv)
{
    const float* W = (blockIdx.z == 0) ? Wq : (blockIdx.z == 1 ? Wk : Wv);
    float*       C = (blockIdx.z == 0) ? g_Q : (blockIdx.z == 1 ? g_K : g_V);

    float c[4][4] = {};
    sgemm64_nt(x, W, c);

    const int tx = threadIdx.x & 15;
    const int ty = threadIdx.x >> 4;
    const int row0 = blockIdx.y * 64;
    const int col0 = blockIdx.x * 64;

    #pragma unroll
    for (int i = 0; i < 4; ++i) {
        const int row = row0 + (ty << 2) + i;
        const int b   = row >> 11;       // /SEQ
        const int s   = row & (SEQ - 1);
        #pragma unroll
        for (int j = 0; j < 4; ++j) {
            const int col = col0 + (tx << 2) + j;
            const int h = col >> 6;
            const int d = col & 63;
            C[(((size_t)(b * HEADS + h) * SEQ) + s) * HEAD_DIM + d] = c[i][j];
        }
    }
}

// Output projection: Y = g_O @ Wo^T + bo
__global__ void out_gemm_kernel(const float* __restrict__ Wo,
                                const float* __restrict__ bo,
                                float* __restrict__ Y)
{
    float c[4][4] = {};
    sgemm64_nt(g_O, Wo, c);

    const int tx = threadIdx.x & 15;
    const int ty = threadIdx.x >> 4;
    const int row0 = blockIdx.y * 64;
    const int col0 = blockIdx.x * 64;

    #pragma unroll
    for (int i = 0; i < 4; ++i) {
        const int row = row0 + (ty << 2) + i;
        #pragma unroll
        for (int j = 0; j < 4; ++j) {
            const int col = col0 + (tx << 2) + j;
            Y[(size_t)row * HIDDEN + col] = c[i][j] + bo[col];
        }
    }
}

// ---------------------------------------------------------------------------
// Attention: one block per (b,h,q)-row. 256 threads.
//   1) scores[j] = q . K[j] / 8
//   2) bitonic sort copy (descending) -> kth = 1024th largest
//   3) gate = max(kth, clip(thr,0,1));  keep iff score >= gate
//   4) masked softmax, then out[d] = sum_j p_j * V[j,d]
// ---------------------------------------------------------------------------
__global__ void attn_kernel(const float* __restrict__ thr_ptr)
{
    const int s_q = blockIdx.x;
    const int bh  = blockIdx.y;          // b*HEADS + h
    const int tid = threadIdx.x;

    const float* Kb   = g_K + (size_t)bh * SEQ * HEAD_DIM;
    const float* Vb   = g_V + (size_t)bh * SEQ * HEAD_DIM;
    const float* qrow = g_Q + ((size_t)bh * SEQ + s_q) * HEAD_DIM;

    __shared__ float4 qs[16];
    __shared__ float  sc[SEQ];
    __shared__ float  sb[SEQ];
    __shared__ float  red[256];
    __shared__ float  s_m, s_sum;

    if (tid < 16) qs[tid] = ((const float4*)qrow)[tid];
    __syncthreads();

    // ---- scores ----
    for (int j = tid; j < SEQ; j += 256) {
        const float4* kr = (const float4*)(Kb + (size_t)j * HEAD_DIM);
        float acc = 0.f;
        #pragma unroll
        for (int t = 0; t < 16; ++t) {
            float4 kv = kr[t];
            float4 qv = qs[t];
            acc += kv.x * qv.x + kv.y * qv.y + kv.z * qv.z + kv.w * qv.w;
        }
        float s = acc * 0.125f;   // 1/sqrt(64)
        sc[j] = s;
        sb[j] = s;
    }
    __syncthreads();

    // ---- bitonic sort (descending) of sb ----
    for (int k = 2; k <= SEQ; k <<= 1) {
        for (int j2 = k >> 1; j2 > 0; j2 >>= 1) {
            #pragma unroll 1
            for (int i = tid; i < SEQ; i += 256) {
                const int ixj = i ^ j2;
                if (ixj > i) {
                    const float a = sb[i], b = sb[ixj];
                    const bool desc = ((i & k) == 0);
                    if (desc ? (a < b) : (a > b)) { sb[i] = b; sb[ixj] = a; }
                }
            }
            __syncthreads();
        }
    }
    const float kth  = sb[KKEEP - 1];
    const float thr  = fminf(fmaxf(*thr_ptr, 0.f), 1.f);
    const float gate = fmaxf(kth, thr);   // keep iff s >= kth && s >= thr

    // ---- max over kept ----
    float lm = -INFINITY;
    for (int j = tid; j < SEQ; j += 256) {
        const float s = sc[j];
        if (s >= gate) lm = fmaxf(lm, s);
    }
    red[tid] = lm;
    __syncthreads();
    for (int o = 128; o > 0; o >>= 1) {
        if (tid < o) red[tid] = fmaxf(red[tid], red[tid + o]);
        __syncthreads();
    }
    if (tid == 0) s_m = red[0];
    __syncthreads();
    const float m = s_m;

    // ---- exp + sum (p stored in sb) ----
    float ls = 0.f;
    for (int j = tid; j < SEQ; j += 256) {
        const float s = sc[j];
        const float p = (s >= gate) ? __expf(s - m) : 0.f;
        sb[j] = p;
        ls += p;
    }
    red[tid] = ls;
    __syncthreads();
    for (int o = 128; o > 0; o >>= 1) {
        if (tid < o) red[tid] += red[tid + o];
        __syncthreads();
    }
    if (tid == 0) s_sum = red[0];
    __syncthreads();
    const float inv = 1.f / s_sum;

    // ---- out[d] = sum_j p_j * V[j,d] ; 4 j-groups x 64 dims ----
    const int d = tid & 63;
    const int g = tid >> 6;
    float acc = 0.f;
    for (int j = g * (SEQ / 4); j < (g + 1) * (SEQ / 4); ++j) {
        const float p = sb[j];         // warp-uniform -> no divergence
        if (p != 0.f)
            acc = fmaf(p, Vb[(size_t)j * HEAD_DIM + d], acc);
    }
    red[tid] = acc;
    __syncthreads();
    if (tid < 64) {
        const float o = (red[tid] + red[tid + 64] + red[tid + 128] + red[tid + 192]) * inv;
        const int b = bh >> 4;
        const int h = bh & 15;
        g_O[(((size_t)b * SEQ + s_q) * HIDDEN) + h * HEAD_DIM + d] = o;
    }
}

// ---------------------------------------------------------------------------
extern "C" void kernel_launch(void* const* d_in, const int* in_sizes, int n_in,
                              void* d_out, int out_size)
{
    const float* x   = (const float*)d_in[0];
    const float* Wq  = (const float*)d_in[1];
    const float* Wk  = (const float*)d_in[2];
    const float* Wv  = (const float*)d_in[3];
    const float* Wo  = (const float*)d_in[4];
    const float* bo  = (const float*)d_in[5];
    const float* thr = (const float*)d_in[6];
    float* out = (float*)d_out;

    dim3 gqkv(HIDDEN / 64, MROWS / 64, 3);
    qkv_gemm_kernel<<<gqkv, 256>>>(x, Wq, Wk, Wv);

    dim3 ga(SEQ, BATCH * HEADS);
    attn_kernel<<<ga, 256>>>(thr);

    dim3 go(HIDDEN / 64, MROWS / 64);
    out_gemm_kernel<<<go, 256>>>(Wo, bo, out);
}

// round 2
// speedup vs baseline: 8.1948x; 8.1948x over previous
#include <cuda_runtime.h>
#include <math.h>

#define HIDDEN   1024
#define HEADS    16
#define HEAD_DIM 64
#define BATCH    2
#define SEQ      2048
#define MROWS    (BATCH*SEQ)     // 4096
#define BH       (BATCH*HEADS)   // 32
#define KKEEP    1024            // max(1, int(S * (1 - 0.5)))

// ---------------------------------------------------------------------------
// Scratch (device globals; no runtime allocation allowed)
// ---------------------------------------------------------------------------
__device__ float g_Q[(size_t)BH*SEQ*HEAD_DIM];   // [bh,s,d] 16MB
__device__ float g_K[(size_t)BH*SEQ*HEAD_DIM];
__device__ float g_V[(size_t)BH*SEQ*HEAD_DIM];
__device__ float g_O[(size_t)MROWS*HIDDEN];      // [b,s,hidden] 16MB
__device__ float g_S[(size_t)BH*SEQ*SEQ];        // scores/probs, 512MB

// ---------------------------------------------------------------------------
// Generic 64x64 fp32 GEMM-NT tile: C[r,c] = sum_k A[r,k]*W[c,k]
// block = 256 threads, 4x4 micro-tile per thread. smem padded to kill
// 4-way store bank conflicts.
// ---------------------------------------------------------------------------
#define SPAD 66

__device__ __forceinline__ void sgemm_nt(const float* __restrict__ A, int lda,
                                         const float* __restrict__ W, int ldw,
                                         int kdepth, int row0, int col0,
                                         float c[4][4])
{
    __shared__ float As[16][SPAD];
    __shared__ float Bs[16][SPAD];

    const int tid = threadIdx.x;
    const int lr  = tid >> 2;          // 0..63
    const int lc  = (tid & 3) << 2;    // 0,4,8,12
    const int tx  = tid & 15;
    const int ty  = tid >> 4;

    for (int k0 = 0; k0 < kdepth; k0 += 16) {
        float4 av = *(const float4*)(A + (size_t)(row0 + lr) * lda + k0 + lc);
        float4 bv = *(const float4*)(W + (size_t)(col0 + lr) * ldw + k0 + lc);
        As[lc + 0][lr] = av.x; As[lc + 1][lr] = av.y;
        As[lc + 2][lr] = av.z; As[lc + 3][lr] = av.w;
        Bs[lc + 0][lr] = bv.x; Bs[lc + 1][lr] = bv.y;
        Bs[lc + 2][lr] = bv.z; Bs[lc + 3][lr] = bv.w;
        __syncthreads();

        #pragma unroll
        for (int kk = 0; kk < 16; ++kk) {
            float a[4], b[4];
            #pragma unroll
            for (int i = 0; i < 4; ++i) a[i] = As[kk][(ty << 2) + i];
            #pragma unroll
            for (int j = 0; j < 4; ++j) b[j] = Bs[kk][(tx << 2) + j];
            #pragma unroll
            for (int i = 0; i < 4; ++i)
                #pragma unroll
                for (int j = 0; j < 4; ++j)
                    c[i][j] = fmaf(a[i], b[j], c[i][j]);
        }
        __syncthreads();
    }
}

// ---------------------------------------------------------------------------
// QKV projections -> Q/K/V in [bh, s, d]
// ---------------------------------------------------------------------------
__global__ void qkv_gemm_kernel(const float* __restrict__ x,
                                const float* __restrict__ Wq,
                                const float* __restrict__ Wk,
                                const float* __restrict__ Wv)
{
    const float* W = (blockIdx.z == 0) ? Wq : (blockIdx.z == 1 ? Wk : Wv);
    float*       C = (blockIdx.z == 0) ? g_Q : (blockIdx.z == 1 ? g_K : g_V);
    const int row0 = blockIdx.y * 64;
    const int col0 = blockIdx.x * 64;

    float c[4][4] = {};
    sgemm_nt(x, HIDDEN, W, HIDDEN, HIDDEN, row0, col0, c);

    const int tx = threadIdx.x & 15;
    const int ty = threadIdx.x >> 4;
    #pragma unroll
    for (int i = 0; i < 4; ++i) {
        const int row = row0 + (ty << 2) + i;
        const int b   = row >> 11;
        const int s   = row & (SEQ - 1);
        #pragma unroll
        for (int j = 0; j < 4; ++j) {
            const int col = col0 + (tx << 2) + j;
            const int h = col >> 6;
            const int d = col & 63;
            C[(((size_t)(b * HEADS + h) * SEQ) + s) * HEAD_DIM + d] = c[i][j];
        }
    }
}

// ---------------------------------------------------------------------------
// Scores: S[bh, q, j] = (Q[bh,q,:] . K[bh,j,:]) / 8
// grid: (SEQ/64 jtiles, SEQ/64 qtiles, BH)
// ---------------------------------------------------------------------------
__global__ void scores_gemm_kernel()
{
    const int bh   = blockIdx.z;
    const int row0 = blockIdx.y * 64;
    const int col0 = blockIdx.x * 64;
    const float* Qb = g_Q + (size_t)bh * SEQ * HEAD_DIM;
    const float* Kb = g_K + (size_t)bh * SEQ * HEAD_DIM;
    float*       Sb = g_S + (size_t)bh * SEQ * SEQ;

    float c[4][4] = {};
    sgemm_nt(Qb, HEAD_DIM, Kb, HEAD_DIM, HEAD_DIM, row0, col0, c);

    const int tx = threadIdx.x & 15;
    const int ty = threadIdx.x >> 4;
    #pragma unroll
    for (int i = 0; i < 4; ++i) {
        const int q = row0 + (ty << 2) + i;
        #pragma unroll
        for (int j = 0; j < 4; ++j)
            Sb[(size_t)q * SEQ + col0 + (tx << 2) + j] = c[i][j] * 0.125f;
    }
}

// ---------------------------------------------------------------------------
// Per-row radix select (exact kth largest) + masked softmax, in place on g_S.
// One block (256 thr) per row; 8 scores per thread held in registers.
// ---------------------------------------------------------------------------
__device__ __forceinline__ unsigned f2u(float f) {
    unsigned b = __float_as_uint(f);
    return (b & 0x80000000u) ? ~b : (b | 0x80000000u);
}

__global__ void select_softmax_kernel(const float* __restrict__ thr_ptr)
{
    const int tid = threadIdx.x;
    float* Srow = g_S + (size_t)blockIdx.x * SEQ;

    __shared__ unsigned hist[256];
    __shared__ unsigned wsum[8];
    __shared__ float    red[8];
    __shared__ unsigned s_pref;
    __shared__ int      s_kk;
    __shared__ float    s_scalar;

    // load 8 scores per thread (two coalesced float4 per thread)
    float4 v0 = ((const float4*)Srow)[tid];
    float4 v1 = ((const float4*)Srow)[256 + tid];
    float s[8] = {v0.x, v0.y, v0.z, v0.w, v1.x, v1.y, v1.z, v1.w};
    unsigned u[8];
    #pragma unroll
    for (int t = 0; t < 8; ++t) u[t] = f2u(s[t]);

    const int lane = tid & 31;
    const int wrp  = tid >> 5;

    // ---- row max (needed for softmax) ----
    float lm = s[0];
    #pragma unroll
    for (int t = 1; t < 8; ++t) lm = fmaxf(lm, s[t]);
    #pragma unroll
    for (int o = 16; o > 0; o >>= 1) lm = fmaxf(lm, __shfl_xor_sync(0xFFFFFFFFu, lm, o));
    if (lane == 0) red[wrp] = lm;
    __syncthreads();
    if (tid == 0) {
        float m = red[0];
        #pragma unroll
        for (int w = 1; w < 8; ++w) m = fmaxf(m, red[w]);
        s_scalar = m;
    }
    __syncthreads();
    const float m = s_scalar;

    // ---- radix select: kth (KKEEP) largest orderable key ----
    unsigned pref = 0;
    int kk = KKEEP;
    #pragma unroll
    for (int shift = 24; shift >= 0; shift -= 8) {
        hist[tid] = 0;
        __syncthreads();
        #pragma unroll
        for (int t = 0; t < 8; ++t) {
            bool ok = (shift == 24) || ((u[t] >> (shift + 8)) == (pref >> (shift + 8)));
            if (ok) atomicAdd(&hist[(u[t] >> shift) & 0xFFu], 1u);
        }
        __syncthreads();
        // suffix scan over 256 bins: cum[b] = sum_{b'>=b} hist[b']
        unsigned myc = hist[tid];
        unsigned cum = myc;
        #pragma unroll
        for (int o = 1; o < 32; o <<= 1) {
            unsigned g = __shfl_down_sync(0xFFFFFFFFu, cum, o);
            if (lane + o < 32) cum += g;
        }
        if (lane == 0) wsum[wrp] = cum;   // warp suffix total (from its lane0)
        cum = __shfl_sync(0xFFFFFFFFu, cum, lane); // keep per-lane suffix
        __syncthreads();
        unsigned above = 0;
        #pragma unroll
        for (int w = 0; w < 8; ++w) if (w > wrp) above += wsum[w];
        cum += above;                      // full suffix sum over bins >= tid
        if (cum >= (unsigned)kk && (cum - myc) < (unsigned)kk) {
            s_pref = pref | ((unsigned)tid << shift);
            s_kk   = kk - (int)(cum - myc);
        }
        __syncthreads();
        pref = s_pref;
        kk   = s_kk;
        __syncthreads();
    }

    // kth-largest value back to float
    const unsigned fb = (pref & 0x80000000u) ? (pref & 0x7FFFFFFFu) : ~pref;
    const float kthf  = __uint_as_float(fb);
    const float thr   = fminf(fmaxf(*thr_ptr, 0.f), 1.f);
    const float gate  = fmaxf(kthf, thr);   // keep iff s >= kth && s >= thr

    // ---- masked exp + sum ----
    float p[8];
    float ls = 0.f;
    #pragma unroll
    for (int t = 0; t < 8; ++t) {
        p[t] = (s[t] >= gate) ? __expf(s[t] - m) : 0.f;
        ls += p[t];
    }
    #pragma unroll
    for (int o = 16; o > 0; o >>= 1) ls += __shfl_xor_sync(0xFFFFFFFFu, ls, o);
    if (lane == 0) red[wrp] = ls;
    __syncthreads();
    if (tid == 0) {
        float t0 = 0.f;
        #pragma unroll
        for (int w = 0; w < 8; ++w) t0 += red[w];
        s_scalar = 1.f / t0;
    }
    __syncthreads();
    const float inv = s_scalar;

    ((float4*)Srow)[tid]       = make_float4(p[0]*inv, p[1]*inv, p[2]*inv, p[3]*inv);
    ((float4*)Srow)[256 + tid] = make_float4(p[4]*inv, p[5]*inv, p[6]*inv, p[7]*inv);
}

// ---------------------------------------------------------------------------
// AV GEMM (NN): O[bh, q, d] = sum_j P[bh,q,j] * V[bh,j,d]
// grid: (SEQ/64 qtiles, BH). Writes g_O [b,s,hidden].
// ---------------------------------------------------------------------------
__global__ void av_gemm_kernel()
{
    const int bh   = blockIdx.y;
    const int row0 = blockIdx.x * 64;
    const float* Pb = g_S + (size_t)bh * SEQ * SEQ;
    const float* Vb = g_V + (size_t)bh * SEQ * HEAD_DIM;

    __shared__ float As[16][SPAD];
    __shared__ float Bs[16][SPAD];

    const int tid = threadIdx.x;
    const int lr  = tid >> 2;
    const int lc  = (tid & 3) << 2;
    const int tx  = tid & 15;
    const int ty  = tid >> 4;

    float c[4][4] = {};
    for (int k0 = 0; k0 < SEQ; k0 += 16) {
        float4 av = *(const float4*)(Pb + (size_t)(row0 + lr) * SEQ + k0 + lc);
        As[lc + 0][lr] = av.x; As[lc + 1][lr] = av.y;
        As[lc + 2][lr] = av.z; As[lc + 3][lr] = av.w;
        // V tile: Bs[kk][d] = V[(k0+kk)*64 + d]
        {
            const int kk = tid >> 4;          // 0..15
            const int d4 = (tid & 15) << 2;   // 0..60
            float4 bv = *(const float4*)(Vb + (size_t)(k0 + kk) * HEAD_DIM + d4);
            Bs[kk][d4 + 0] = bv.x; Bs[kk][d4 + 1] = bv.y;
            Bs[kk][d4 + 2] = bv.z; Bs[kk][d4 + 3] = bv.w;
        }
        __syncthreads();

        #pragma unroll
        for (int kk = 0; kk < 16; ++kk) {
            float a[4], b[4];
            #pragma unroll
            for (int i = 0; i < 4; ++i) a[i] = As[kk][(ty << 2) + i];
            #pragma unroll
            for (int j = 0; j < 4; ++j) b[j] = Bs[kk][(tx << 2) + j];
            #pragma unroll
            for (int i = 0; i < 4; ++i)
                #pragma unroll
                for (int j = 0; j < 4; ++j)
                    c[i][j] = fmaf(a[i], b[j], c[i][j]);
        }
        __syncthreads();
    }

    const int b = bh >> 4;
    const int h = bh & 15;
    #pragma unroll
    for (int i = 0; i < 4; ++i) {
        const int q = row0 + (ty << 2) + i;
        #pragma unroll
        for (int j = 0; j < 4; ++j) {
            const int d = (tx << 2) + j;
            g_O[(((size_t)b * SEQ + q) * HIDDEN) + h * HEAD_DIM + d] = c[i][j];
        }
    }
}

// ---------------------------------------------------------------------------
// Output projection: Y = g_O @ Wo^T + bo
// ---------------------------------------------------------------------------
__global__ void out_gemm_kernel(const float* __restrict__ Wo,
                                const float* __restrict__ bo,
                                float* __restrict__ Y)
{
    const int row0 = blockIdx.y * 64;
    const int col0 = blockIdx.x * 64;
    float c[4][4] = {};
    sgemm_nt(g_O, HIDDEN, Wo, HIDDEN, HIDDEN, row0, col0, c);

    const int tx = threadIdx.x & 15;
    const int ty = threadIdx.x >> 4;
    #pragma unroll
    for (int i = 0; i < 4; ++i) {
        const int row = row0 + (ty << 2) + i;
        #pragma unroll
        for (int j = 0; j < 4; ++j) {
            const int col = col0 + (tx << 2) + j;
            Y[(size_t)row * HIDDEN + col] = c[i][j] + bo[col];
        }
    }
}

// ---------------------------------------------------------------------------
extern "C" void kernel_launch(void* const* d_in, const int* in_sizes, int n_in,
                              void* d_out, int out_size)
{
    const float* x   = (const float*)d_in[0];
    const float* Wq  = (const float*)d_in[1];
    const float* Wk  = (const float*)d_in[2];
    const float* Wv  = (const float*)d_in[3];
    const float* Wo  = (const float*)d_in[4];
    const float* bo  = (const float*)d_in[5];
    const float* thr = (const float*)d_in[6];
    float* out = (float*)d_out;

    dim3 gqkv(HIDDEN / 64, MROWS / 64, 3);
    qkv_gemm_kernel<<<gqkv, 256>>>(x, Wq, Wk, Wv);

    dim3 gs(SEQ / 64, SEQ / 64, BH);
    scores_gemm_kernel<<<gs, 256>>>();

    select_softmax_kernel<<<BH * SEQ, 256>>>(thr);

    dim3 gav(SEQ / 64, BH);
    av_gemm_kernel<<<gav, 256>>>();

    dim3 go(HIDDEN / 64, MROWS / 64);
    out_gemm_kernel<<<go, 256>>>(Wo, bo, out);
}

// round 3
// speedup vs baseline: 9.0654x; 1.1062x over previous
#include <cuda_runtime.h>
#include <math.h>

#define HIDDEN   1024
#define HEADS    16
#define HEAD_DIM 64
#define BATCH    2
#define SEQ      2048
#define MROWS    (BATCH*SEQ)     // 4096
#define BH       (BATCH*HEADS)   // 32
#define KKEEP    1024            // max(1, int(S * (1 - 0.5)))

// ---------------------------------------------------------------------------
// Scratch (device globals; no runtime allocation allowed)
// ---------------------------------------------------------------------------
__device__ float  g_Q[(size_t)BH*SEQ*HEAD_DIM];   // [bh,s,d] 16MB
__device__ float  g_K[(size_t)BH*SEQ*HEAD_DIM];
__device__ float  g_V[(size_t)BH*SEQ*HEAD_DIM];
__device__ float  g_O[(size_t)MROWS*HIDDEN];      // [b,s,hidden] 16MB
__device__ float  g_S[(size_t)BH*SEQ*SEQ];        // raw scores, 512MB
__device__ float4 g_par[(size_t)BH*SEQ];          // per row: (gate, m, inv, 0)

#define PADA 132   // 132*4 bytes: multiple of 16 -> aligned float4 smem reads

// ---------------------------------------------------------------------------
// 128x128x16 fp32 GEMM-NT core: C[r,c] = sum_k A[r,k] * B[c,k]
// 256 threads, 8x8 micro-tile per thread (split 4+4 across 64-row halves).
// ---------------------------------------------------------------------------
__device__ __forceinline__ void gemm128_nt(const float* __restrict__ A, int lda,
                                           const float* __restrict__ B, int ldb,
                                           int kdepth, int row0, int col0,
                                           float c[8][8])
{
    __shared__ float As[16][PADA];
    __shared__ float Bs[16][PADA];

    const int tid = threadIdx.x;
    const int lr  = tid >> 1;          // 0..127
    const int lk  = (tid & 1) << 3;    // 0 or 8
    const int tx  = tid & 15;
    const int ty  = tid >> 4;

    for (int k0 = 0; k0 < kdepth; k0 += 16) {
        const float* ap = A + (size_t)(row0 + lr) * lda + k0 + lk;
        const float* bp = B + (size_t)(col0 + lr) * ldb + k0 + lk;
        float4 a0 = *(const float4*)ap;
        float4 a1 = *(const float4*)(ap + 4);
        float4 b0 = *(const float4*)bp;
        float4 b1 = *(const float4*)(bp + 4);
        As[lk+0][lr]=a0.x; As[lk+1][lr]=a0.y; As[lk+2][lr]=a0.z; As[lk+3][lr]=a0.w;
        As[lk+4][lr]=a1.x; As[lk+5][lr]=a1.y; As[lk+6][lr]=a1.z; As[lk+7][lr]=a1.w;
        Bs[lk+0][lr]=b0.x; Bs[lk+1][lr]=b0.y; Bs[lk+2][lr]=b0.z; Bs[lk+3][lr]=b0.w;
        Bs[lk+4][lr]=b1.x; Bs[lk+5][lr]=b1.y; Bs[lk+6][lr]=b1.z; Bs[lk+7][lr]=b1.w;
        __syncthreads();

        #pragma unroll
        for (int kk = 0; kk < 16; ++kk) {
            float4 av0 = *(const float4*)&As[kk][ty << 2];
            float4 av1 = *(const float4*)&As[kk][64 + (ty << 2)];
            float4 bv0 = *(const float4*)&Bs[kk][tx << 2];
            float4 bv1 = *(const float4*)&Bs[kk][64 + (tx << 2)];
            float ar[8] = {av0.x, av0.y, av0.z, av0.w, av1.x, av1.y, av1.z, av1.w};
            float br[8] = {bv0.x, bv0.y, bv0.z, bv0.w, bv1.x, bv1.y, bv1.z, bv1.w};
            #pragma unroll
            for (int i = 0; i < 8; ++i)
                #pragma unroll
                for (int j = 0; j < 8; ++j)
                    c[i][j] = fmaf(ar[i], br[j], c[i][j]);
        }
        __syncthreads();
    }
}

__device__ __forceinline__ int map_row(int ty, int i) {
    return (i < 4) ? ((ty << 2) + i) : (64 + (ty << 2) + i - 4);
}

// ---------------------------------------------------------------------------
// QKV projections -> Q/K/V in [bh, s, d]
// ---------------------------------------------------------------------------
__global__ void qkv_gemm_kernel(const float* __restrict__ x,
                                const float* __restrict__ Wq,
                                const float* __restrict__ Wk,
                                const float* __restrict__ Wv)
{
    const float* W = (blockIdx.z == 0) ? Wq : (blockIdx.z == 1 ? Wk : Wv);
    float*       C = (blockIdx.z == 0) ? g_Q : (blockIdx.z == 1 ? g_K : g_V);
    const int row0 = blockIdx.y * 128;
    const int col0 = blockIdx.x * 128;

    float c[8][8] = {};
    gemm128_nt(x, HIDDEN, W, HIDDEN, HIDDEN, row0, col0, c);

    const int tx = threadIdx.x & 15;
    const int ty = threadIdx.x >> 4;
    #pragma unroll
    for (int i = 0; i < 8; ++i) {
        const int row = row0 + map_row(ty, i);
        const int b   = row >> 11;
        const int s   = row & (SEQ - 1);
        #pragma unroll
        for (int g = 0; g < 2; ++g) {
            const int col = col0 + g * 64 + (tx << 2);
            const int h = col >> 6;
            const int d = col & 63;
            float4 v = make_float4(c[i][g*4+0], c[i][g*4+1], c[i][g*4+2], c[i][g*4+3]);
            *(float4*)&C[(((size_t)(b * HEADS + h) * SEQ) + s) * HEAD_DIM + d] = v;
        }
    }
}

// ---------------------------------------------------------------------------
// Scores: S[bh, q, j] = (Q[bh,q,:] . K[bh,j,:]) / 8
// ---------------------------------------------------------------------------
__global__ void scores_gemm_kernel()
{
    const int bh   = blockIdx.z;
    const int row0 = blockIdx.y * 128;
    const int col0 = blockIdx.x * 128;
    const float* Qb = g_Q + (size_t)bh * SEQ * HEAD_DIM;
    const float* Kb = g_K + (size_t)bh * SEQ * HEAD_DIM;
    float*       Sb = g_S + (size_t)bh * SEQ * SEQ;

    float c[8][8] = {};
    gemm128_nt(Qb, HEAD_DIM, Kb, HEAD_DIM, HEAD_DIM, row0, col0, c);

    const int tx = threadIdx.x & 15;
    const int ty = threadIdx.x >> 4;
    #pragma unroll
    for (int i = 0; i < 8; ++i) {
        const int q = row0 + map_row(ty, i);
        #pragma unroll
        for (int g = 0; g < 2; ++g) {
            float4 v = make_float4(c[i][g*4+0]*0.125f, c[i][g*4+1]*0.125f,
                                   c[i][g*4+2]*0.125f, c[i][g*4+3]*0.125f);
            *(float4*)&Sb[(size_t)q * SEQ + col0 + g * 64 + (tx << 2)] = v;
        }
    }
}

// ---------------------------------------------------------------------------
// Per-row radix select (exact kth largest). Writes (gate, m, inv) per row.
// One block (256 thr) per row; 8 scores per thread in registers.
// Histogram atomics are warp-aggregated via __match_any_sync.
// ---------------------------------------------------------------------------
__device__ __forceinline__ unsigned f2u(float f) {
    unsigned b = __float_as_uint(f);
    return (b & 0x80000000u) ? ~b : (b | 0x80000000u);
}

__global__ void select_kernel(const float* __restrict__ thr_ptr)
{
    const int tid = threadIdx.x;
    const float* Srow = g_S + (size_t)blockIdx.x * SEQ;

    __shared__ unsigned hist[256];
    __shared__ unsigned wsum[8];
    __shared__ float    red[8];
    __shared__ unsigned s_pref;
    __shared__ int      s_kk;
    __shared__ float    s_scalar;

    float4 v0 = ((const float4*)Srow)[tid];
    float4 v1 = ((const float4*)Srow)[256 + tid];
    float s[8] = {v0.x, v0.y, v0.z, v0.w, v1.x, v1.y, v1.z, v1.w};
    unsigned u[8];
    #pragma unroll
    for (int t = 0; t < 8; ++t) u[t] = f2u(s[t]);

    const int lane = tid & 31;
    const int wrp  = tid >> 5;

    // ---- row max ----
    float lm = s[0];
    #pragma unroll
    for (int t = 1; t < 8; ++t) lm = fmaxf(lm, s[t]);
    #pragma unroll
    for (int o = 16; o > 0; o >>= 1) lm = fmaxf(lm, __shfl_xor_sync(0xFFFFFFFFu, lm, o));
    if (lane == 0) red[wrp] = lm;
    __syncthreads();
    if (tid == 0) {
        float m0 = red[0];
        #pragma unroll
        for (int w = 1; w < 8; ++w) m0 = fmaxf(m0, red[w]);
        s_scalar = m0;
    }
    __syncthreads();
    const float m = s_scalar;

    // ---- radix select kth largest ----
    unsigned pref = 0;
    int kk = KKEEP;
    #pragma unroll
    for (int shift = 24; shift >= 0; shift -= 8) {
        hist[tid] = 0;
        __syncthreads();
        #pragma unroll
        for (int t = 0; t < 8; ++t) {
            const bool ok = (shift == 24) ||
                            ((u[t] >> (shift + 8)) == (pref >> (shift + 8)));
            const unsigned mok = __ballot_sync(0xFFFFFFFFu, ok);
            if (mok) {
                const unsigned bin = (u[t] >> shift) & 0xFFu;
                const unsigned key = ok ? bin : (256u + (unsigned)lane);
                const unsigned peers = __match_any_sync(0xFFFFFFFFu, key);
                if (ok && lane == (__ffs(peers) - 1))
                    atomicAdd(&hist[bin], (unsigned)__popc(peers));
            }
        }
        __syncthreads();
        // suffix scan: cum[b] = sum_{b' >= b} hist[b']
        unsigned myc = hist[tid];
        unsigned cum = myc;
        #pragma unroll
        for (int o = 1; o < 32; o <<= 1) {
            unsigned g = __shfl_down_sync(0xFFFFFFFFu, cum, o);
            if (lane + o < 32) cum += g;
        }
        if (lane == 0) wsum[wrp] = cum;
        __syncthreads();
        unsigned above = 0;
        #pragma unroll
        for (int w = 0; w < 8; ++w) if (w > wrp) above += wsum[w];
        cum += above;
        if (cum >= (unsigned)kk && (cum - myc) < (unsigned)kk) {
            s_pref = pref | ((unsigned)tid << shift);
            s_kk   = kk - (int)(cum - myc);
        }
        __syncthreads();
        pref = s_pref;
        kk   = s_kk;
        __syncthreads();
    }

    const unsigned fb = (pref & 0x80000000u) ? (pref & 0x7FFFFFFFu) : ~pref;
    const float kthf  = __uint_as_float(fb);
    const float thr   = fminf(fmaxf(*thr_ptr, 0.f), 1.f);
    const float gate  = fmaxf(kthf, thr);

    // ---- sum of exp over kept ----
    float ls = 0.f;
    #pragma unroll
    for (int t = 0; t < 8; ++t)
        ls += (s[t] >= gate) ? __expf(s[t] - m) : 0.f;
    #pragma unroll
    for (int o = 16; o > 0; o >>= 1) ls += __shfl_xor_sync(0xFFFFFFFFu, ls, o);
    if (lane == 0) red[wrp] = ls;
    __syncthreads();
    if (tid == 0) {
        float t0 = 0.f;
        #pragma unroll
        for (int w = 0; w < 8; ++w) t0 += red[w];
        g_par[blockIdx.x] = make_float4(gate, m, 1.f / t0, 0.f);
    }
}

// ---------------------------------------------------------------------------
// AV with fused gating+softmax: O[q,d] = inv * sum_j exp-gated(S[q,j]) * V[j,d]
// 128(q) x 64(d) tile, 256 thr, 8x4 micro-tile.
// ---------------------------------------------------------------------------
__global__ void av_gemm_kernel()
{
    const int bh   = blockIdx.y;
    const int row0 = blockIdx.x * 128;
    const float* Sb = g_S + (size_t)bh * SEQ * SEQ;
    const float* Vb = g_V + (size_t)bh * SEQ * HEAD_DIM;

    __shared__ float As[16][PADA];
    __shared__ float Bs[16][68];

    const int tid = threadIdx.x;
    const int lr  = tid >> 1;
    const int lk  = (tid & 1) << 3;
    const int kr  = tid >> 4;          // 0..15 (V tile row)
    const int nc  = (tid & 15) << 2;   // 0..60
    const int tx  = tid & 15;
    const int ty  = tid >> 4;

    const float4 par = g_par[(size_t)bh * SEQ + row0 + lr];
    const float gate = par.x, mrow = par.y;

    float c[8][4] = {};
    for (int k0 = 0; k0 < SEQ; k0 += 16) {
        const float* sp = Sb + (size_t)(row0 + lr) * SEQ + k0 + lk;
        float4 a0 = *(const float4*)sp;
        float4 a1 = *(const float4*)(sp + 4);
        float pe[8];
        pe[0]=a0.x; pe[1]=a0.y; pe[2]=a0.z; pe[3]=a0.w;
        pe[4]=a1.x; pe[5]=a1.y; pe[6]=a1.z; pe[7]=a1.w;
        #pragma unroll
        for (int t = 0; t < 8; ++t)
            pe[t] = (pe[t] >= gate) ? __expf(pe[t] - mrow) : 0.f;
        #pragma unroll
        for (int t = 0; t < 8; ++t) As[lk + t][lr] = pe[t];

        float4 bv = *(const float4*)(Vb + (size_t)(k0 + kr) * HEAD_DIM + nc);
        *(float4*)&Bs[kr][nc] = bv;
        __syncthreads();

        #pragma unroll
        for (int kk = 0; kk < 16; ++kk) {
            float4 av0 = *(const float4*)&As[kk][ty << 2];
            float4 av1 = *(const float4*)&As[kk][64 + (ty << 2)];
            float4 bv0 = *(const float4*)&Bs[kk][tx << 2];
            float ar[8] = {av0.x, av0.y, av0.z, av0.w, av1.x, av1.y, av1.z, av1.w};
            float br[4] = {bv0.x, bv0.y, bv0.z, bv0.w};
            #pragma unroll
            for (int i = 0; i < 8; ++i)
                #pragma unroll
                for (int j = 0; j < 4; ++j)
                    c[i][j] = fmaf(ar[i], br[j], c[i][j]);
        }
        __syncthreads();
    }

    const int b = bh >> 4;
    const int h = bh & 15;
    #pragma unroll
    for (int i = 0; i < 8; ++i) {
        const int q   = row0 + map_row(ty, i);
        const float inv = g_par[(size_t)bh * SEQ + q].z;
        float4 v = make_float4(c[i][0]*inv, c[i][1]*inv, c[i][2]*inv, c[i][3]*inv);
        *(float4*)&g_O[(((size_t)b * SEQ + q) * HIDDEN) + h * HEAD_DIM + (tx << 2)] = v;
    }
}

// ---------------------------------------------------------------------------
// Output projection: Y = g_O @ Wo^T + bo
// ---------------------------------------------------------------------------
__global__ void out_gemm_kernel(const float* __restrict__ Wo,
                                const float* __restrict__ bo,
                                float* __restrict__ Y)
{
    const int row0 = blockIdx.y * 128;
    const int col0 = blockIdx.x * 128;
    float c[8][8] = {};
    gemm128_nt(g_O, HIDDEN, Wo, HIDDEN, HIDDEN, row0, col0, c);

    const int tx = threadIdx.x & 15;
    const int ty = threadIdx.x >> 4;
    #pragma unroll
    for (int i = 0; i < 8; ++i) {
        const int row = row0 + map_row(ty, i);
        #pragma unroll
        for (int g = 0; g < 2; ++g) {
            const int col = col0 + g * 64 + (tx << 2);
            float4 v = make_float4(c[i][g*4+0] + bo[col+0], c[i][g*4+1] + bo[col+1],
                                   c[i][g*4+2] + bo[col+2], c[i][g*4+3] + bo[col+3]);
            *(float4*)&Y[(size_t)row * HIDDEN + col] = v;
        }
    }
}

// ---------------------------------------------------------------------------
extern "C" void kernel_launch(void* const* d_in, const int* in_sizes, int n_in,
                              void* d_out, int out_size)
{
    const float* x   = (const float*)d_in[0];
    const float* Wq  = (const float*)d_in[1];
    const float* Wk  = (const float*)d_in[2];
    const float* Wv  = (const float*)d_in[3];
    const float* Wo  = (const float*)d_in[4];
    const float* bo  = (const float*)d_in[5];
    const float* thr = (const float*)d_in[6];
    float* out = (float*)d_out;

    dim3 gqkv(HIDDEN / 128, MROWS / 128, 3);
    qkv_gemm_kernel<<<gqkv, 256>>>(x, Wq, Wk, Wv);

    dim3 gs(SEQ / 128, SEQ / 128, BH);
    scores_gemm_kernel<<<gs, 256>>>();

    select_kernel<<<BH * SEQ, 256>>>(thr);

    dim3 gav(SEQ / 128, BH);
    av_gemm_kernel<<<gav, 256>>>();

    dim3 go(HIDDEN / 128, MROWS / 128);
    out_gemm_kernel<<<go, 256>>>(Wo, bo, out);
}

// round 4
// speedup vs baseline: 10.3807x; 1.1451x over previous
#include <cuda_runtime.h>
#include <math.h>

#define HIDDEN   1024
#define HEADS    16
#define HEAD_DIM 64
#define BATCH    2
#define SEQ      2048
#define MROWS    (BATCH*SEQ)     // 4096
#define BH       (BATCH*HEADS)   // 32
#define KKEEP    1024

// ---------------------------------------------------------------------------
// Scratch (device globals; no runtime allocation allowed)
// ---------------------------------------------------------------------------
__device__ float  g_Q[(size_t)BH*SEQ*HEAD_DIM];   // [bh,s,d]
__device__ float  g_K[(size_t)BH*SEQ*HEAD_DIM];
__device__ float  g_V[(size_t)BH*SEQ*HEAD_DIM];
__device__ float  g_O[(size_t)MROWS*HIDDEN];      // [b,s,hidden]
__device__ float  g_S[(size_t)BH*SEQ*SEQ];        // raw scores, 512MB
__device__ float4 g_par[(size_t)BH*SEQ];          // per row: (gate, m, inv, 0)

// ---------------------------------------------------------------------------
// tf32 MMA plumbing (m16n8k8, HMMA path)
// ---------------------------------------------------------------------------
__device__ __forceinline__ unsigned f2tf32(float f) {
    unsigned u;
    asm("cvt.rna.tf32.f32 %0, %1;" : "=r"(u) : "f"(f));
    return u;
}

__device__ __forceinline__ void mma8(float d[4], const uint4& a, const uint2& b) {
    asm("mma.sync.aligned.m16n8k8.row.col.f32.tf32.tf32.f32 "
        "{%0,%1,%2,%3},{%4,%5,%6,%7},{%8,%9},{%0,%1,%2,%3};"
        : "+f"(d[0]), "+f"(d[1]), "+f"(d[2]), "+f"(d[3])
        : "r"(a.x), "r"(a.y), "r"(a.z), "r"(a.w), "r"(b.x), "r"(b.y));
}

// Fragment-packed smem layouts.
//   A (float4 slots): AIDX(mtile, k8, r8, cx)  cx = c ^ (r8&3)   (swizzled)
//   B (float2 slots): BIDX(ntile, k8, n8, c)
__device__ __forceinline__ int AIDX(int mt, int k8, int r8, int cx) {
    return ((((mt << 1) + k8) << 3) + r8) * 4 + cx;
}
__device__ __forceinline__ int BIDX(int nt, int k8, int n8, int c) {
    return ((((nt << 1) + k8) << 3) + n8) * 4 + c;
}

// Fill A fragments from row-major src (128 rows x 16 k). 256 threads.
template<bool X3>
__device__ __forceinline__ void fillA(const float* __restrict__ base, int lda,
                                      uint4* Ah, uint4* Al, int tid)
{
    const int lr = tid >> 1, lk = (tid & 1) << 3;
    const float* p = base + (size_t)lr * lda + lk;
    float4 v0 = *(const float4*)p;
    float4 v1 = *(const float4*)(p + 4);
    float e[8] = {v0.x, v0.y, v0.z, v0.w, v1.x, v1.y, v1.z, v1.w};
    const int mt = lr >> 4, rr = lr & 15, r8 = rr & 7, rh = rr >> 3, k8 = tid & 1;
    #pragma unroll
    for (int j = 0; j < 8; ++j) {
        const int c = j & 3, ch = (j >> 2) & 1;
        const int cx = c ^ (r8 & 3);
        const int comp = rh + (ch << 1);
        const int idx = AIDX(mt, k8, r8, cx);
        const unsigned hi = f2tf32(e[j]);
        ((unsigned*)&Ah[idx])[comp] = hi;
        if (X3) {
            const float lo = e[j] - __uint_as_float(hi);
            ((unsigned*)&Al[idx])[comp] = f2tf32(lo);
        }
    }
}

// Fill A fragments from S with fused gate+exp (AV kernel, x1).
__device__ __forceinline__ void fillA_av(const float* __restrict__ base,
                                         uint4* Ah, int tid, float gate, float m)
{
    const int lr = tid >> 1, lk = (tid & 1) << 3;
    const float* p = base + (size_t)lr * SEQ + lk;
    float4 v0 = *(const float4*)p;
    float4 v1 = *(const float4*)(p + 4);
    float e[8] = {v0.x, v0.y, v0.z, v0.w, v1.x, v1.y, v1.z, v1.w};
    const int mt = lr >> 4, rr = lr & 15, r8 = rr & 7, rh = rr >> 3, k8 = tid & 1;
    #pragma unroll
    for (int j = 0; j < 8; ++j) {
        const float pe = (e[j] >= gate) ? __expf(e[j] - m) : 0.f;
        const int c = j & 3, ch = (j >> 2) & 1;
        const int cx = c ^ (r8 & 3);
        const int comp = rh + (ch << 1);
        ((unsigned*)&Ah[AIDX(mt, k8, r8, cx)])[comp] = f2tf32(pe);
    }
}

// Fill B fragments, NT source (B[n][k] row-major, 128 n x 16 k). 256 threads.
template<bool X3>
__device__ __forceinline__ void fillB_nt(const float* __restrict__ base, int ldb,
                                         uint2* Bh, uint2* Bl, int tid)
{
    const int ln = tid >> 1, lk = (tid & 1) << 3;
    const float* p = base + (size_t)ln * ldb + lk;
    float4 v0 = *(const float4*)p;
    float4 v1 = *(const float4*)(p + 4);
    float e[8] = {v0.x, v0.y, v0.z, v0.w, v1.x, v1.y, v1.z, v1.w};
    const int nt = ln >> 3, n8 = ln & 7, k8 = tid & 1;
    #pragma unroll
    for (int j = 0; j < 8; ++j) {
        const int c = j & 3, ph = (j >> 2) & 1;
        const int idx = BIDX(nt, k8, n8, c);
        const unsigned hi = f2tf32(e[j]);
        ((unsigned*)&Bh[idx])[ph] = hi;
        if (X3) {
            const float lo = e[j] - __uint_as_float(hi);
            ((unsigned*)&Bl[idx])[ph] = f2tf32(lo);
        }
    }
}

// Fill B fragments, NN source (V[k][64], 16 k x 64 n). 256 threads, x1.
__device__ __forceinline__ void fillB_nn(const float* __restrict__ vb,
                                         uint2* Bh, int tid)
{
    const int kr = tid >> 4, nc = (tid & 15) << 2;
    float4 v = *(const float4*)(vb + (size_t)kr * HEAD_DIM + nc);
    float e[4] = {v.x, v.y, v.z, v.w};
    const int k8 = kr >> 3, c = kr & 3, ph = (kr >> 2) & 1;
    #pragma unroll
    for (int j = 0; j < 4; ++j) {
        const int n = nc + j;
        ((unsigned*)&Bh[BIDX(n >> 3, k8, n & 7, c)])[ph] = f2tf32(e[j]);
    }
}

// ---------------------------------------------------------------------------
// QKV projections (tf32x3) -> Q/K/V in [bh, s, d]
// ---------------------------------------------------------------------------
__global__ void __launch_bounds__(256, 2)
qkv_gemm_kernel(const float* __restrict__ x,
                const float* __restrict__ Wq,
                const float* __restrict__ Wk,
                const float* __restrict__ Wv)
{
    __shared__ uint4 Ah[512], Al[512];
    __shared__ uint2 Bh[1024], Bl[1024];

    const float* W = (blockIdx.z == 0) ? Wq : (blockIdx.z == 1 ? Wk : Wv);
    float*       C = (blockIdx.z == 0) ? g_Q : (blockIdx.z == 1 ? g_K : g_V);

    const int tid = threadIdx.x, lane = tid & 31, wid = tid >> 5;
    const int wm = wid >> 1, wn = wid & 1;
    const int row0 = blockIdx.y * 128, col0 = blockIdx.x * 128;
    const int r8 = lane >> 2, cc = lane & 3, cx = cc ^ (r8 & 3);

    float d[2][8][4] = {};
    for (int k0 = 0; k0 < HIDDEN; k0 += 16) {
        fillA<true>(x + (size_t)row0 * HIDDEN + k0, HIDDEN, Ah, Al, tid);
        fillB_nt<true>(W + (size_t)col0 * HIDDEN + k0, HIDDEN, Bh, Bl, tid);
        __syncthreads();
        #pragma unroll
        for (int k8 = 0; k8 < 2; ++k8) {
            uint4 ah[2], al[2];
            #pragma unroll
            for (int mt = 0; mt < 2; ++mt) {
                ah[mt] = Ah[AIDX(wm * 2 + mt, k8, r8, cx)];
                al[mt] = Al[AIDX(wm * 2 + mt, k8, r8, cx)];
            }
            #pragma unroll
            for (int nt = 0; nt < 8; ++nt) {
                const int bi = BIDX(wn * 8 + nt, k8, r8, cc);
                const uint2 bh = Bh[bi], bl = Bl[bi];
                #pragma unroll
                for (int mt = 0; mt < 2; ++mt) {
                    mma8(d[mt][nt], ah[mt], bh);
                    mma8(d[mt][nt], ah[mt], bl);
                    mma8(d[mt][nt], al[mt], bh);
                }
            }
        }
        __syncthreads();
    }

    const int g = lane >> 2, t2 = (lane & 3) << 1;
    #pragma unroll
    for (int mt = 0; mt < 2; ++mt) {
        const int rA = row0 + (wm * 2 + mt) * 16 + g;
        const int rB = rA + 8;
        const int bA = rA >> 11, sA = rA & (SEQ - 1);
        const int bB = rB >> 11, sB = rB & (SEQ - 1);
        #pragma unroll
        for (int nt = 0; nt < 8; ++nt) {
            const int col = col0 + (wn * 8 + nt) * 8 + t2;
            const int h = col >> 6, dd = col & 63;
            *(float2*)&C[(((size_t)(bA * HEADS + h) * SEQ) + sA) * HEAD_DIM + dd] =
                make_float2(d[mt][nt][0], d[mt][nt][1]);
            *(float2*)&C[(((size_t)(bB * HEADS + h) * SEQ) + sB) * HEAD_DIM + dd] =
                make_float2(d[mt][nt][2], d[mt][nt][3]);
        }
    }
}

// ---------------------------------------------------------------------------
// Scores (tf32x3): S[bh,q,j] = (Q . K) / 8
// ---------------------------------------------------------------------------
__global__ void __launch_bounds__(256, 2)
scores_gemm_kernel()
{
    __shared__ uint4 Ah[512], Al[512];
    __shared__ uint2 Bh[1024], Bl[1024];

    const int bh = blockIdx.z;
    const float* Qb = g_Q + (size_t)bh * SEQ * HEAD_DIM;
    const float* Kb = g_K + (size_t)bh * SEQ * HEAD_DIM;
    float*       Sb = g_S + (size_t)bh * SEQ * SEQ;

    const int tid = threadIdx.x, lane = tid & 31, wid = tid >> 5;
    const int wm = wid >> 1, wn = wid & 1;
    const int row0 = blockIdx.y * 128, col0 = blockIdx.x * 128;
    const int r8 = lane >> 2, cc = lane & 3, cx = cc ^ (r8 & 3);

    float d[2][8][4] = {};
    #pragma unroll
    for (int k0 = 0; k0 < HEAD_DIM; k0 += 16) {
        fillA<true>(Qb + (size_t)row0 * HEAD_DIM + k0, HEAD_DIM, Ah, Al, tid);
        fillB_nt<true>(Kb + (size_t)col0 * HEAD_DIM + k0, HEAD_DIM, Bh, Bl, tid);
        __syncthreads();
        #pragma unroll
        for (int k8 = 0; k8 < 2; ++k8) {
            uint4 ah[2], al[2];
            #pragma unroll
            for (int mt = 0; mt < 2; ++mt) {
                ah[mt] = Ah[AIDX(wm * 2 + mt, k8, r8, cx)];
                al[mt] = Al[AIDX(wm * 2 + mt, k8, r8, cx)];
            }
            #pragma unroll
            for (int nt = 0; nt < 8; ++nt) {
                const int bi = BIDX(wn * 8 + nt, k8, r8, cc);
                const uint2 bh2 = Bh[bi], bl2 = Bl[bi];
                #pragma unroll
                for (int mt = 0; mt < 2; ++mt) {
                    mma8(d[mt][nt], ah[mt], bh2);
                    mma8(d[mt][nt], ah[mt], bl2);
                    mma8(d[mt][nt], al[mt], bh2);
                }
            }
        }
        __syncthreads();
    }

    const int g = lane >> 2, t2 = (lane & 3) << 1;
    #pragma unroll
    for (int mt = 0; mt < 2; ++mt) {
        const int qA = row0 + (wm * 2 + mt) * 16 + g;
        const int qB = qA + 8;
        #pragma unroll
        for (int nt = 0; nt < 8; ++nt) {
            const int col = col0 + (wn * 8 + nt) * 8 + t2;
            *(float2*)&Sb[(size_t)qA * SEQ + col] =
                make_float2(d[mt][nt][0] * 0.125f, d[mt][nt][1] * 0.125f);
            *(float2*)&Sb[(size_t)qB * SEQ + col] =
                make_float2(d[mt][nt][2] * 0.125f, d[mt][nt][3] * 0.125f);
        }
    }
}

// ---------------------------------------------------------------------------
// Per-row radix select (exact kth largest) -> (gate, m, inv) per row.
// ---------------------------------------------------------------------------
__device__ __forceinline__ unsigned f2u(float f) {
    unsigned b = __float_as_uint(f);
    return (b & 0x80000000u) ? ~b : (b | 0x80000000u);
}

__global__ void select_kernel(const float* __restrict__ thr_ptr)
{
    const int tid = threadIdx.x;
    const float* Srow = g_S + (size_t)blockIdx.x * SEQ;

    __shared__ unsigned hist[256];
    __shared__ unsigned wsum[8];
    __shared__ float    red[8];
    __shared__ unsigned s_pref;
    __shared__ int      s_kk;
    __shared__ float    s_scalar;

    float4 v0 = ((const float4*)Srow)[tid];
    float4 v1 = ((const float4*)Srow)[256 + tid];
    float s[8] = {v0.x, v0.y, v0.z, v0.w, v1.x, v1.y, v1.z, v1.w};
    unsigned u[8];
    #pragma unroll
    for (int t = 0; t < 8; ++t) u[t] = f2u(s[t]);

    const int lane = tid & 31;
    const int wrp  = tid >> 5;

    float lm = s[0];
    #pragma unroll
    for (int t = 1; t < 8; ++t) lm = fmaxf(lm, s[t]);
    #pragma unroll
    for (int o = 16; o > 0; o >>= 1) lm = fmaxf(lm, __shfl_xor_sync(0xFFFFFFFFu, lm, o));
    if (lane == 0) red[wrp] = lm;
    __syncthreads();
    if (tid == 0) {
        float m0 = red[0];
        #pragma unroll
        for (int w = 1; w < 8; ++w) m0 = fmaxf(m0, red[w]);
        s_scalar = m0;
    }
    __syncthreads();
    const float m = s_scalar;

    unsigned pref = 0;
    int kk = KKEEP;
    #pragma unroll
    for (int shift = 24; shift >= 0; shift -= 8) {
        hist[tid] = 0;
        __syncthreads();
        #pragma unroll
        for (int t = 0; t < 8; ++t) {
            const bool ok = (shift == 24) ||
                            ((u[t] >> (shift + 8)) == (pref >> (shift + 8)));
            const unsigned mok = __ballot_sync(0xFFFFFFFFu, ok);
            if (mok) {
                const unsigned bin = (u[t] >> shift) & 0xFFu;
                const unsigned key = ok ? bin : (256u + (unsigned)lane);
                const unsigned peers = __match_any_sync(0xFFFFFFFFu, key);
                if (ok && lane == (__ffs(peers) - 1))
                    atomicAdd(&hist[bin], (unsigned)__popc(peers));
            }
        }
        __syncthreads();
        unsigned myc = hist[tid];
        unsigned cum = myc;
        #pragma unroll
        for (int o = 1; o < 32; o <<= 1) {
            unsigned g2 = __shfl_down_sync(0xFFFFFFFFu, cum, o);
            if (lane + o < 32) cum += g2;
        }
        if (lane == 0) wsum[wrp] = cum;
        __syncthreads();
        unsigned above = 0;
        #pragma unroll
        for (int w = 0; w < 8; ++w) if (w > wrp) above += wsum[w];
        cum += above;
        if (cum >= (unsigned)kk && (cum - myc) < (unsigned)kk) {
            s_pref = pref | ((unsigned)tid << shift);
            s_kk   = kk - (int)(cum - myc);
        }
        __syncthreads();
        pref = s_pref;
        kk   = s_kk;
        __syncthreads();
    }

    const unsigned fb = (pref & 0x80000000u) ? (pref & 0x7FFFFFFFu) : ~pref;
    const float kthf  = __uint_as_float(fb);
    const float thr   = fminf(fmaxf(*thr_ptr, 0.f), 1.f);
    const float gate  = fmaxf(kthf, thr);

    float ls = 0.f;
    #pragma unroll
    for (int t = 0; t < 8; ++t)
        ls += (s[t] >= gate) ? __expf(s[t] - m) : 0.f;
    #pragma unroll
    for (int o = 16; o > 0; o >>= 1) ls += __shfl_xor_sync(0xFFFFFFFFu, ls, o);
    if (lane == 0) red[wrp] = ls;
    __syncthreads();
    if (tid == 0) {
        float t0 = 0.f;
        #pragma unroll
        for (int w = 0; w < 8; ++w) t0 += red[w];
        g_par[blockIdx.x] = make_float4(gate, m, 1.f / t0, 0.f);
    }
}

// ---------------------------------------------------------------------------
// AV (tf32, fused gate+softmax): O[q,d] = inv * sum_j p(S[q,j]) * V[j,d]
// 128(q) x 64(d), K = 2048.
// ---------------------------------------------------------------------------
__global__ void __launch_bounds__(256, 2)
av_gemm_kernel()
{
    __shared__ uint4 Ah[512];
    __shared__ uint2 Bh[512];

    const int bh   = blockIdx.y;
    const int row0 = blockIdx.x * 128;
    const float* Sb = g_S + (size_t)bh * SEQ * SEQ;
    const float* Vb = g_V + (size_t)bh * SEQ * HEAD_DIM;

    const int tid = threadIdx.x, lane = tid & 31, wid = tid >> 5;
    const int wm = wid >> 1, wn = wid & 1;
    const int r8 = lane >> 2, cc = lane & 3, cx = cc ^ (r8 & 3);

    const float4 par = g_par[(size_t)bh * SEQ + row0 + (tid >> 1)];
    const float gate = par.x, mrow = par.y;

    float d[2][4][4] = {};
    for (int k0 = 0; k0 < SEQ; k0 += 16) {
        fillA_av(Sb + (size_t)row0 * SEQ + k0, Ah, tid, gate, mrow);
        fillB_nn(Vb + (size_t)k0 * HEAD_DIM, Bh, tid);
        __syncthreads();
        #pragma unroll
        for (int k8 = 0; k8 < 2; ++k8) {
            uint4 ah[2];
            #pragma unroll
            for (int mt = 0; mt < 2; ++mt)
                ah[mt] = Ah[AIDX(wm * 2 + mt, k8, r8, cx)];
            #pragma unroll
            for (int nt = 0; nt < 4; ++nt) {
                const uint2 bv = Bh[BIDX(wn * 4 + nt, k8, r8, cc)];
                #pragma unroll
                for (int mt = 0; mt < 2; ++mt)
                    mma8(d[mt][nt], ah[mt], bv);
            }
        }
        __syncthreads();
    }

    const int b = bh >> 4, h = bh & 15;
    const int g = lane >> 2, t2 = (lane & 3) << 1;
    #pragma unroll
    for (int mt = 0; mt < 2; ++mt) {
        const int qA = row0 + (wm * 2 + mt) * 16 + g;
        const int qB = qA + 8;
        const float invA = g_par[(size_t)bh * SEQ + qA].z;
        const float invB = g_par[(size_t)bh * SEQ + qB].z;
        #pragma unroll
        for (int nt = 0; nt < 4; ++nt) {
            const int col = (wn * 4 + nt) * 8 + t2;
            *(float2*)&g_O[(((size_t)b * SEQ + qA) * HIDDEN) + h * HEAD_DIM + col] =
                make_float2(d[mt][nt][0] * invA, d[mt][nt][1] * invA);
            *(float2*)&g_O[(((size_t)b * SEQ + qB) * HIDDEN) + h * HEAD_DIM + col] =
                make_float2(d[mt][nt][2] * invB, d[mt][nt][3] * invB);
        }
    }
}

// ---------------------------------------------------------------------------
// Output projection (tf32): Y = g_O @ Wo^T + bo
// ---------------------------------------------------------------------------
__global__ void __launch_bounds__(256, 2)
out_gemm_kernel(const float* __restrict__ Wo,
                const float* __restrict__ bo,
                float* __restrict__ Y)
{
    __shared__ uint4 Ah[512];
    __shared__ uint2 Bh[1024];

    const int tid = threadIdx.x, lane = tid & 31, wid = tid >> 5;
    const int wm = wid >> 1, wn = wid & 1;
    const int row0 = blockIdx.y * 128, col0 = blockIdx.x * 128;
    const int r8 = lane >> 2, cc = lane & 3, cx = cc ^ (r8 & 3);

    float d[2][8][4] = {};
    for (int k0 = 0; k0 < HIDDEN; k0 += 16) {
        fillA<false>(g_O + (size_t)row0 * HIDDEN + k0, HIDDEN, Ah, Ah, tid);
        fillB_nt<false>(Wo + (size_t)col0 * HIDDEN + k0, HIDDEN, Bh, Bh, tid);
        __syncthreads();
        #pragma unroll
        for (int k8 = 0; k8 < 2; ++k8) {
            uint4 ah[2];
            #pragma unroll
            for (int mt = 0; mt < 2; ++mt)
                ah[mt] = Ah[AIDX(wm * 2 + mt, k8, r8, cx)];
            #pragma unroll
            for (int nt = 0; nt < 8; ++nt) {
                const uint2 bv = Bh[BIDX(wn * 8 + nt, k8, r8, cc)];
                #pragma unroll
                for (int mt = 0; mt < 2; ++mt)
                    mma8(d[mt][nt], ah[mt], bv);
            }
        }
        __syncthreads();
    }

    const int g = lane >> 2, t2 = (lane & 3) << 1;
    #pragma unroll
    for (int mt = 0; mt < 2; ++mt) {
        const int rA = row0 + (wm * 2 + mt) * 16 + g;
        const int rB = rA + 8;
        #pragma unroll
        for (int nt = 0; nt < 8; ++nt) {
            const int col = col0 + (wn * 8 + nt) * 8 + t2;
            const float b0 = bo[col], b1 = bo[col + 1];
            *(float2*)&Y[(size_t)rA * HIDDEN + col] =
                make_float2(d[mt][nt][0] + b0, d[mt][nt][1] + b1);
            *(float2*)&Y[(size_t)rB * HIDDEN + col] =
                make_float2(d[mt][nt][2] + b0, d[mt][nt][3] + b1);
        }
    }
}

// ---------------------------------------------------------------------------
extern "C" void kernel_launch(void* const* d_in, const int* in_sizes, int n_in,
                              void* d_out, int out_size)
{
    const float* x   = (const float*)d_in[0];
    const float* Wq  = (const float*)d_in[1];
    const float* Wk  = (const float*)d_in[2];
    const float* Wv  = (const float*)d_in[3];
    const float* Wo  = (const float*)d_in[4];
    const float* bo  = (const float*)d_in[5];
    const float* thr = (const float*)d_in[6];
    float* out = (float*)d_out;

    dim3 gqkv(HIDDEN / 128, MROWS / 128, 3);
    qkv_gemm_kernel<<<gqkv, 256>>>(x, Wq, Wk, Wv);

    dim3 gs(SEQ / 128, SEQ / 128, BH);
    scores_gemm_kernel<<<gs, 256>>>();

    select_kernel<<<BH * SEQ, 256>>>(thr);

    dim3 gav(SEQ / 128, BH);
    av_gemm_kernel<<<gav, 256>>>();

    dim3 go(HIDDEN / 128, MROWS / 128);
    out_gemm_kernel<<<go, 256>>>(Wo, bo, out);
}

// round 5
// speedup vs baseline: 10.6338x; 1.0244x over previous
#include <cuda_runtime.h>
#include <math.h>

#define HIDDEN   1024
#define HEADS    16
#define HEAD_DIM 64
#define BATCH    2
#define SEQ      2048
#define MROWS    (BATCH*SEQ)     // 4096
#define BH       (BATCH*HEADS)   // 32
#define KKEEP    1024

// ---------------------------------------------------------------------------
// Scratch (device globals; no runtime allocation allowed)
// ---------------------------------------------------------------------------
__device__ float  g_Q[(size_t)BH*SEQ*HEAD_DIM];   // [bh,s,d]
__device__ float  g_K[(size_t)BH*SEQ*HEAD_DIM];
__device__ float  g_V[(size_t)BH*SEQ*HEAD_DIM];
__device__ float  g_O[(size_t)MROWS*HIDDEN];      // [b,s,hidden]
__device__ float  g_S[(size_t)BH*SEQ*SEQ];        // raw scores, 512MB
__device__ float4 g_par[(size_t)BH*SEQ];          // per row: (gate, m, inv, 0)

// ---------------------------------------------------------------------------
// tf32 MMA plumbing (m16n8k8)
// ---------------------------------------------------------------------------
__device__ __forceinline__ unsigned f2tf32(float f) {
    unsigned u;
    asm("cvt.rna.tf32.f32 %0, %1;" : "=r"(u) : "f"(f));
    return u;
}

__device__ __forceinline__ void mma8(float d[4], const uint4& a, const uint2& b) {
    asm("mma.sync.aligned.m16n8k8.row.col.f32.tf32.tf32.f32 "
        "{%0,%1,%2,%3},{%4,%5,%6,%7},{%8,%9},{%0,%1,%2,%3};"
        : "+f"(d[0]), "+f"(d[1]), "+f"(d[2]), "+f"(d[3])
        : "r"(a.x), "r"(a.y), "r"(a.z), "r"(a.w), "r"(b.x), "r"(b.y));
}

__device__ __forceinline__ int AIDX(int mt, int k8, int r8, int cx) {
    return ((((mt << 1) + k8) << 3) + r8) * 4 + cx;
}
__device__ __forceinline__ int BIDX(int nt, int k8, int n8, int c) {
    return ((((nt << 1) + k8) << 3) + n8) * 4 + c;
}

// ---- raw 8-float row load ----
__device__ __forceinline__ void ldrow(const float* __restrict__ p, float e[8]) {
    float4 a = *(const float4*)p;
    float4 b = *(const float4*)(p + 4);
    e[0]=a.x; e[1]=a.y; e[2]=a.z; e[3]=a.w;
    e[4]=b.x; e[5]=b.y; e[6]=b.z; e[7]=b.w;
}

// ---- pack raw floats into fragment smem ----
template<bool X3>
__device__ __forceinline__ void packA(const float e[8], uint4* Ah, uint4* Al, int tid)
{
    const int lr = tid >> 1;
    const int mt = lr >> 4, rr = lr & 15, r8 = rr & 7, rh = rr >> 3, k8 = tid & 1;
    #pragma unroll
    for (int j = 0; j < 8; ++j) {
        const int c = j & 3, ch = (j >> 2) & 1;
        const int cx = c ^ (r8 & 3);
        const int comp = rh + (ch << 1);
        const int idx = AIDX(mt, k8, r8, cx);
        const unsigned hi = f2tf32(e[j]);
        ((unsigned*)&Ah[idx])[comp] = hi;
        if (X3)
            ((unsigned*)&Al[idx])[comp] = f2tf32(e[j] - __uint_as_float(hi));
    }
}

__device__ __forceinline__ void packA_av(const float e[8], uint4* Ah, int tid,
                                         float gate, float m)
{
    const int lr = tid >> 1;
    const int mt = lr >> 4, rr = lr & 15, r8 = rr & 7, rh = rr >> 3, k8 = tid & 1;
    #pragma unroll
    for (int j = 0; j < 8; ++j) {
        const float pe = (e[j] >= gate) ? __expf(e[j] - m) : 0.f;
        const int c = j & 3, ch = (j >> 2) & 1;
        const int cx = c ^ (r8 & 3);
        const int comp = rh + (ch << 1);
        ((unsigned*)&Ah[AIDX(mt, k8, r8, cx)])[comp] = f2tf32(pe);
    }
}

template<bool X3>
__device__ __forceinline__ void packB_nt(const float e[8], uint2* Bh, uint2* Bl, int tid)
{
    const int ln = tid >> 1;
    const int nt = ln >> 3, n8 = ln & 7, k8 = tid & 1;
    #pragma unroll
    for (int j = 0; j < 8; ++j) {
        const int c = j & 3, ph = (j >> 2) & 1;
        const int idx = BIDX(nt, k8, n8, c);
        const unsigned hi = f2tf32(e[j]);
        ((unsigned*)&Bh[idx])[ph] = hi;
        if (X3)
            ((unsigned*)&Bl[idx])[ph] = f2tf32(e[j] - __uint_as_float(hi));
    }
}

// V (NN: 16k x 64n) pack, x1
__device__ __forceinline__ void packB_nn(const float e[4], uint2* Bh, int tid)
{
    const int kr = tid >> 4, nc = (tid & 15) << 2;
    const int k8 = kr >> 3, c = kr & 3, ph = (kr >> 2) & 1;
    #pragma unroll
    for (int j = 0; j < 4; ++j) {
        const int n = nc + j;
        ((unsigned*)&Bh[BIDX(n >> 3, k8, n & 7, c)])[ph] = f2tf32(e[j]);
    }
}

// ---------------------------------------------------------------------------
// QKV projections (tf32x3, pipelined) -> Q/K/V in [bh, s, d]
// ---------------------------------------------------------------------------
__global__ void __launch_bounds__(256, 2)
qkv_gemm_kernel(const float* __restrict__ x,
                const float* __restrict__ Wq,
                const float* __restrict__ Wk,
                const float* __restrict__ Wv)
{
    __shared__ uint4 Ah[2][512], Al[2][512];
    __shared__ uint2 Bh[2][1024], Bl[2][1024];

    const float* W = (blockIdx.z == 0) ? Wq : (blockIdx.z == 1 ? Wk : Wv);
    float*       C = (blockIdx.z == 0) ? g_Q : (blockIdx.z == 1 ? g_K : g_V);

    const int tid = threadIdx.x, lane = tid & 31, wid = tid >> 5;
    const int wm = wid >> 1, wn = wid & 1;
    const int row0 = blockIdx.y * 128, col0 = blockIdx.x * 128;
    const int r8 = lane >> 2, cc = lane & 3, cx = cc ^ (r8 & 3);
    const int lr = tid >> 1, lk = (tid & 1) << 3;

    const float* Ab = x + (size_t)(row0 + lr) * HIDDEN + lk;
    const float* Bb = W + (size_t)(col0 + lr) * HIDDEN + lk;

    float ea[8], eb[8];
    ldrow(Ab, ea); ldrow(Bb, eb);
    packA<true>(ea, Ah[0], Al[0], tid);
    packB_nt<true>(eb, Bh[0], Bl[0], tid);
    __syncthreads();

    float d[2][8][4] = {};
    for (int k0 = 0; k0 < HIDDEN; k0 += 16) {
        const int cur = (k0 >> 4) & 1, nxt = cur ^ 1;
        const bool more = (k0 + 16) < HIDDEN;
        if (more) { ldrow(Ab + k0 + 16, ea); ldrow(Bb + k0 + 16, eb); }

        #pragma unroll
        for (int k8 = 0; k8 < 2; ++k8) {
            uint4 ah[2], al[2];
            #pragma unroll
            for (int mt = 0; mt < 2; ++mt) {
                ah[mt] = Ah[cur][AIDX(wm * 2 + mt, k8, r8, cx)];
                al[mt] = Al[cur][AIDX(wm * 2 + mt, k8, r8, cx)];
            }
            #pragma unroll
            for (int nt = 0; nt < 8; ++nt) {
                const int bi = BIDX(wn * 8 + nt, k8, r8, cc);
                const uint2 bhv = Bh[cur][bi], blv = Bl[cur][bi];
                #pragma unroll
                for (int mt = 0; mt < 2; ++mt) {
                    mma8(d[mt][nt], ah[mt], bhv);
                    mma8(d[mt][nt], ah[mt], blv);
                    mma8(d[mt][nt], al[mt], bhv);
                }
            }
        }
        if (more) {
            packA<true>(ea, Ah[nxt], Al[nxt], tid);
            packB_nt<true>(eb, Bh[nxt], Bl[nxt], tid);
        }
        __syncthreads();
    }

    const int g = lane >> 2, t2 = (lane & 3) << 1;
    #pragma unroll
    for (int mt = 0; mt < 2; ++mt) {
        const int rA = row0 + (wm * 2 + mt) * 16 + g;
        const int rB = rA + 8;
        const int bA = rA >> 11, sA = rA & (SEQ - 1);
        const int bB = rB >> 11, sB = rB & (SEQ - 1);
        #pragma unroll
        for (int nt = 0; nt < 8; ++nt) {
            const int col = col0 + (wn * 8 + nt) * 8 + t2;
            const int h = col >> 6, dd = col & 63;
            *(float2*)&C[(((size_t)(bA * HEADS + h) * SEQ) + sA) * HEAD_DIM + dd] =
                make_float2(d[mt][nt][0], d[mt][nt][1]);
            *(float2*)&C[(((size_t)(bB * HEADS + h) * SEQ) + sB) * HEAD_DIM + dd] =
                make_float2(d[mt][nt][2], d[mt][nt][3]);
        }
    }
}

// ---------------------------------------------------------------------------
// Scores (tf32x3, pipelined): S[bh,q,j] = (Q . K) / 8
// ---------------------------------------------------------------------------
__global__ void __launch_bounds__(256, 2)
scores_gemm_kernel()
{
    __shared__ uint4 Ah[2][512], Al[2][512];
    __shared__ uint2 Bh[2][1024], Bl[2][1024];

    const int bh = blockIdx.z;
    const float* Qb = g_Q + (size_t)bh * SEQ * HEAD_DIM;
    const float* Kb = g_K + (size_t)bh * SEQ * HEAD_DIM;
    float*       Sb = g_S + (size_t)bh * SEQ * SEQ;

    const int tid = threadIdx.x, lane = tid & 31, wid = tid >> 5;
    const int wm = wid >> 1, wn = wid & 1;
    const int row0 = blockIdx.y * 128, col0 = blockIdx.x * 128;
    const int r8 = lane >> 2, cc = lane & 3, cx = cc ^ (r8 & 3);
    const int lr = tid >> 1, lk = (tid & 1) << 3;

    const float* Ab = Qb + (size_t)(row0 + lr) * HEAD_DIM + lk;
    const float* Bb = Kb + (size_t)(col0 + lr) * HEAD_DIM + lk;

    float ea[8], eb[8];
    ldrow(Ab, ea); ldrow(Bb, eb);
    packA<true>(ea, Ah[0], Al[0], tid);
    packB_nt<true>(eb, Bh[0], Bl[0], tid);
    __syncthreads();

    float d[2][8][4] = {};
    #pragma unroll
    for (int k0 = 0; k0 < HEAD_DIM; k0 += 16) {
        const int cur = (k0 >> 4) & 1, nxt = cur ^ 1;
        const bool more = (k0 + 16) < HEAD_DIM;
        if (more) { ldrow(Ab + k0 + 16, ea); ldrow(Bb + k0 + 16, eb); }

        #pragma unroll
        for (int k8 = 0; k8 < 2; ++k8) {
            uint4 ah[2], al[2];
            #pragma unroll
            for (int mt = 0; mt < 2; ++mt) {
                ah[mt] = Ah[cur][AIDX(wm * 2 + mt, k8, r8, cx)];
                al[mt] = Al[cur][AIDX(wm * 2 + mt, k8, r8, cx)];
            }
            #pragma unroll
            for (int nt = 0; nt < 8; ++nt) {
                const int bi = BIDX(wn * 8 + nt, k8, r8, cc);
                const uint2 bhv = Bh[cur][bi], blv = Bl[cur][bi];
                #pragma unroll
                for (int mt = 0; mt < 2; ++mt) {
                    mma8(d[mt][nt], ah[mt], bhv);
                    mma8(d[mt][nt], ah[mt], blv);
                    mma8(d[mt][nt], al[mt], bhv);
                }
            }
        }
        if (more) {
            packA<true>(ea, Ah[nxt], Al[nxt], tid);
            packB_nt<true>(eb, Bh[nxt], Bl[nxt], tid);
        }
        __syncthreads();
    }

    const int g = lane >> 2, t2 = (lane & 3) << 1;
    #pragma unroll
    for (int mt = 0; mt < 2; ++mt) {
        const int qA = row0 + (wm * 2 + mt) * 16 + g;
        const int qB = qA + 8;
        #pragma unroll
        for (int nt = 0; nt < 8; ++nt) {
            const int col = col0 + (wn * 8 + nt) * 8 + t2;
            *(float2*)&Sb[(size_t)qA * SEQ + col] =
                make_float2(d[mt][nt][0] * 0.125f, d[mt][nt][1] * 0.125f);
            *(float2*)&Sb[(size_t)qB * SEQ + col] =
                make_float2(d[mt][nt][2] * 0.125f, d[mt][nt][3] * 0.125f);
        }
    }
}

// ---------------------------------------------------------------------------
// Per-row radix select (exact kth largest) -> (gate, m, inv) per row.
// ---------------------------------------------------------------------------
__device__ __forceinline__ unsigned f2u(float f) {
    unsigned b = __float_as_uint(f);
    return (b & 0x80000000u) ? ~b : (b | 0x80000000u);
}

__global__ void select_kernel(const float* __restrict__ thr_ptr)
{
    const int tid = threadIdx.x;
    const float* Srow = g_S + (size_t)blockIdx.x * SEQ;

    __shared__ unsigned hist[256];
    __shared__ unsigned wsum[8];
    __shared__ float    red[8];
    __shared__ unsigned s_pref;
    __shared__ int      s_kk;
    __shared__ float    s_scalar;

    float4 v0 = ((const float4*)Srow)[tid];
    float4 v1 = ((const float4*)Srow)[256 + tid];
    float s[8] = {v0.x, v0.y, v0.z, v0.w, v1.x, v1.y, v1.z, v1.w};
    unsigned u[8];
    #pragma unroll
    for (int t = 0; t < 8; ++t) u[t] = f2u(s[t]);

    const int lane = tid & 31;
    const int wrp  = tid >> 5;

    float lm = s[0];
    #pragma unroll
    for (int t = 1; t < 8; ++t) lm = fmaxf(lm, s[t]);
    #pragma unroll
    for (int o = 16; o > 0; o >>= 1) lm = fmaxf(lm, __shfl_xor_sync(0xFFFFFFFFu, lm, o));
    if (lane == 0) red[wrp] = lm;
    __syncthreads();
    if (tid == 0) {
        float m0 = red[0];
        #pragma unroll
        for (int w = 1; w < 8; ++w) m0 = fmaxf(m0, red[w]);
        s_scalar = m0;
    }
    __syncthreads();
    const float m = s_scalar;

    unsigned pref = 0;
    int kk = KKEEP;
    #pragma unroll
    for (int shift = 24; shift >= 0; shift -= 8) {
        hist[tid] = 0;
        __syncthreads();
        #pragma unroll
        for (int t = 0; t < 8; ++t) {
            const bool ok = (shift == 24) ||
                            ((u[t] >> (shift + 8)) == (pref >> (shift + 8)));
            const unsigned mok = __ballot_sync(0xFFFFFFFFu, ok);
            if (mok) {
                const unsigned bin = (u[t] >> shift) & 0xFFu;
                const unsigned key = ok ? bin : (256u + (unsigned)lane);
                const unsigned peers = __match_any_sync(0xFFFFFFFFu, key);
                if (ok && lane == (__ffs(peers) - 1))
                    atomicAdd(&hist[bin], (unsigned)__popc(peers));
            }
        }
        __syncthreads();
        unsigned myc = hist[tid];
        unsigned cum = myc;
        #pragma unroll
        for (int o = 1; o < 32; o <<= 1) {
            unsigned g2 = __shfl_down_sync(0xFFFFFFFFu, cum, o);
            if (lane + o < 32) cum += g2;
        }
        if (lane == 0) wsum[wrp] = cum;
        __syncthreads();
        unsigned above = 0;
        #pragma unroll
        for (int w = 0; w < 8; ++w) if (w > wrp) above += wsum[w];
        cum += above;
        if (cum >= (unsigned)kk && (cum - myc) < (unsigned)kk) {
            s_pref = pref | ((unsigned)tid << shift);
            s_kk   = kk - (int)(cum - myc);
        }
        __syncthreads();
        pref = s_pref;
        kk   = s_kk;
        __syncthreads();
    }

    const unsigned fb = (pref & 0x80000000u) ? (pref & 0x7FFFFFFFu) : ~pref;
    const float kthf  = __uint_as_float(fb);
    const float thr   = fminf(fmaxf(*thr_ptr, 0.f), 1.f);
    const float gate  = fmaxf(kthf, thr);

    float ls = 0.f;
    #pragma unroll
    for (int t = 0; t < 8; ++t)
        ls += (s[t] >= gate) ? __expf(s[t] - m) : 0.f;
    #pragma unroll
    for (int o = 16; o > 0; o >>= 1) ls += __shfl_xor_sync(0xFFFFFFFFu, ls, o);
    if (lane == 0) red[wrp] = ls;
    __syncthreads();
    if (tid == 0) {
        float t0 = 0.f;
        #pragma unroll
        for (int w = 0; w < 8; ++w) t0 += red[w];
        g_par[blockIdx.x] = make_float4(gate, m, 1.f / t0, 0.f);
    }
}

// ---------------------------------------------------------------------------
// AV (tf32, fused gate+softmax, pipelined)
// ---------------------------------------------------------------------------
__global__ void __launch_bounds__(256, 2)
av_gemm_kernel()
{
    __shared__ uint4 Ah[2][512];
    __shared__ uint2 Bh[2][512];

    const int bh   = blockIdx.y;
    const int row0 = blockIdx.x * 128;
    const float* Sb = g_S + (size_t)bh * SEQ * SEQ;
    const float* Vb = g_V + (size_t)bh * SEQ * HEAD_DIM;

    const int tid = threadIdx.x, lane = tid & 31, wid = tid >> 5;
    const int wm = wid >> 1, wn = wid & 1;
    const int r8 = lane >> 2, cc = lane & 3, cx = cc ^ (r8 & 3);
    const int lr = tid >> 1, lk = (tid & 1) << 3;
    const int kr = tid >> 4, nc = (tid & 15) << 2;

    const float4 par = g_par[(size_t)bh * SEQ + row0 + lr];
    const float gate = par.x, mrow = par.y;

    const float* Ab = Sb + (size_t)(row0 + lr) * SEQ + lk;
    const float* Bb = Vb + (size_t)kr * HEAD_DIM + nc;

    float ea[8];
    float evb[4];
    ldrow(Ab, ea);
    { float4 v = *(const float4*)Bb; evb[0]=v.x; evb[1]=v.y; evb[2]=v.z; evb[3]=v.w; }
    packA_av(ea, Ah[0], tid, gate, mrow);
    packB_nn(evb, Bh[0], tid);
    __syncthreads();

    float d[2][4][4] = {};
    for (int k0 = 0; k0 < SEQ; k0 += 16) {
        const int cur = (k0 >> 4) & 1, nxt = cur ^ 1;
        const bool more = (k0 + 16) < SEQ;
        if (more) {
            ldrow(Ab + k0 + 16, ea);
            float4 v = *(const float4*)(Bb + (size_t)(k0 + 16) * HEAD_DIM);
            evb[0]=v.x; evb[1]=v.y; evb[2]=v.z; evb[3]=v.w;
        }

        #pragma unroll
        for (int k8 = 0; k8 < 2; ++k8) {
            uint4 ah[2];
            #pragma unroll
            for (int mt = 0; mt < 2; ++mt)
                ah[mt] = Ah[cur][AIDX(wm * 2 + mt, k8, r8, cx)];
            #pragma unroll
            for (int nt = 0; nt < 4; ++nt) {
                const uint2 bv = Bh[cur][BIDX(wn * 4 + nt, k8, r8, cc)];
                #pragma unroll
                for (int mt = 0; mt < 2; ++mt)
                    mma8(d[mt][nt], ah[mt], bv);
            }
        }
        if (more) {
            packA_av(ea, Ah[nxt], tid, gate, mrow);
            packB_nn(evb, Bh[nxt], tid);
        }
        __syncthreads();
    }

    const int b = bh >> 4, h = bh & 15;
    const int g = lane >> 2, t2 = (lane & 3) << 1;
    #pragma unroll
    for (int mt = 0; mt < 2; ++mt) {
        const int qA = row0 + (wm * 2 + mt) * 16 + g;
        const int qB = qA + 8;
        const float invA = g_par[(size_t)bh * SEQ + qA].z;
        const float invB = g_par[(size_t)bh * SEQ + qB].z;
        #pragma unroll
        for (int nt = 0; nt < 4; ++nt) {
            const int col = (wn * 4 + nt) * 8 + t2;
            *(float2*)&g_O[(((size_t)b * SEQ + qA) * HIDDEN) + h * HEAD_DIM + col] =
                make_float2(d[mt][nt][0] * invA, d[mt][nt][1] * invA);
            *(float2*)&g_O[(((size_t)b * SEQ + qB) * HIDDEN) + h * HEAD_DIM + col] =
                make_float2(d[mt][nt][2] * invB, d[mt][nt][3] * invB);
        }
    }
}

// ---------------------------------------------------------------------------
// Output projection (tf32, pipelined): Y = g_O @ Wo^T + bo
// ---------------------------------------------------------------------------
__global__ void __launch_bounds__(256, 2)
out_gemm_kernel(const float* __restrict__ Wo,
                const float* __restrict__ bo,
                float* __restrict__ Y)
{
    __shared__ uint4 Ah[2][512];
    __shared__ uint2 Bh[2][1024];

    const int tid = threadIdx.x, lane = tid & 31, wid = tid >> 5;
    const int wm = wid >> 1, wn = wid & 1;
    const int row0 = blockIdx.y * 128, col0 = blockIdx.x * 128;
    const int r8 = lane >> 2, cc = lane & 3, cx = cc ^ (r8 & 3);
    const int lr = tid >> 1, lk = (tid & 1) << 3;

    const float* Ab = g_O + (size_t)(row0 + lr) * HIDDEN + lk;
    const float* Bb = Wo  + (size_t)(col0 + lr) * HIDDEN + lk;

    float ea[8], eb[8];
    ldrow(Ab, ea); ldrow(Bb, eb);
    packA<false>(ea, Ah[0], Ah[0], tid);
    packB_nt<false>(eb, Bh[0], Bh[0], tid);
    __syncthreads();

    float d[2][8][4] = {};
    for (int k0 = 0; k0 < HIDDEN; k0 += 16) {
        const int cur = (k0 >> 4) & 1, nxt = cur ^ 1;
        const bool more = (k0 + 16) < HIDDEN;
        if (more) { ldrow(Ab + k0 + 16, ea); ldrow(Bb + k0 + 16, eb); }

        #pragma unroll
        for (int k8 = 0; k8 < 2; ++k8) {
            uint4 ah[2];
            #pragma unroll
            for (int mt = 0; mt < 2; ++mt)
                ah[mt] = Ah[cur][AIDX(wm * 2 + mt, k8, r8, cx)];
            #pragma unroll
            for (int nt = 0; nt < 8; ++nt) {
                const uint2 bv = Bh[cur][BIDX(wn * 8 + nt, k8, r8, cc)];
                #pragma unroll
                for (int mt = 0; mt < 2; ++mt)
                    mma8(d[mt][nt], ah[mt], bv);
            }
        }
        if (more) {
            packA<false>(ea, Ah[nxt], Ah[nxt], tid);
            packB_nt<false>(eb, Bh[nxt], Bh[nxt], tid);
        }
        __syncthreads();
    }

    const int g = lane >> 2, t2 = (lane & 3) << 1;
    #pragma unroll
    for (int mt = 0; mt < 2; ++mt) {
        const int rA = row0 + (wm * 2 + mt) * 16 + g;
        const int rB = rA + 8;
        #pragma unroll
        for (int nt = 0; nt < 8; ++nt) {
            const int col = col0 + (wn * 8 + nt) * 8 + t2;
            const float b0 = bo[col], b1 = bo[col + 1];
            *(float2*)&Y[(size_t)rA * HIDDEN + col] =
                make_float2(d[mt][nt][0] + b0, d[mt][nt][1] + b1);
            *(float2*)&Y[(size_t)rB * HIDDEN + col] =
                make_float2(d[mt][nt][2] + b0, d[mt][nt][3] + b1);
        }
    }
}

// ---------------------------------------------------------------------------
extern "C" void kernel_launch(void* const* d_in, const int* in_sizes, int n_in,
                              void* d_out, int out_size)
{
    const float* x   = (const float*)d_in[0];
    const float* Wq  = (const float*)d_in[1];
    const float* Wk  = (const float*)d_in[2];
    const float* Wv  = (const float*)d_in[3];
    const float* Wo  = (const float*)d_in[4];
    const float* bo  = (const float*)d_in[5];
    const float* thr = (const float*)d_in[6];
    float* out = (float*)d_out;

    dim3 gqkv(HIDDEN / 128, MROWS / 128, 3);
    qkv_gemm_kernel<<<gqkv, 256>>>(x, Wq, Wk, Wv);

    dim3 gs(SEQ / 128, SEQ / 128, BH);
    scores_gemm_kernel<<<gs, 256>>>();

    select_kernel<<<BH * SEQ, 256>>>(thr);

    dim3 gav(SEQ / 128, BH);
    av_gemm_kernel<<<gav, 256>>>();

    dim3 go(HIDDEN / 128, MROWS / 128);
    out_gemm_kernel<<<go, 256>>>(Wo, bo, out);
}

// round 6
// speedup vs baseline: 13.4166x; 1.2617x over previous
#include <cuda_runtime.h>
#include <cuda_bf16.h>
#include <math.h>

#define HIDDEN   1024
#define HEADS    16
#define HEAD_DIM 64
#define BATCH    2
#define SEQ      2048
#define MROWS    (BATCH*SEQ)     // 4096
#define BH       (BATCH*HEADS)   // 32
#define KKEEP    1024

// ---------------------------------------------------------------------------
// Scratch (device globals; no runtime allocation allowed)
// ---------------------------------------------------------------------------
__device__ float    g_Q[(size_t)BH*SEQ*HEAD_DIM];
__device__ float    g_K[(size_t)BH*SEQ*HEAD_DIM];
__device__ float    g_V[(size_t)BH*SEQ*HEAD_DIM];
__device__ float    g_O[(size_t)MROWS*HIDDEN];
__device__ float    g_S[(size_t)BH*SEQ*SEQ];            // fp32 scores, 512MB
__device__ unsigned g_key16[(size_t)BH*SEQ*SEQ/2];      // u16 orderable keys, 256MB
__device__ float4   g_par[(size_t)BH*SEQ];              // (kthbits as float, m~, 0, 0)

// ---------------------------------------------------------------------------
// MMA plumbing
// ---------------------------------------------------------------------------
__device__ __forceinline__ unsigned f2tf32(float f) {
    unsigned u;
    asm("cvt.rna.tf32.f32 %0, %1;" : "=r"(u) : "f"(f));
    return u;
}
__device__ __forceinline__ void mma8(float d[4], const uint4& a, const uint2& b) {
    asm("mma.sync.aligned.m16n8k8.row.col.f32.tf32.tf32.f32 "
        "{%0,%1,%2,%3},{%4,%5,%6,%7},{%8,%9},{%0,%1,%2,%3};"
        : "+f"(d[0]), "+f"(d[1]), "+f"(d[2]), "+f"(d[3])
        : "r"(a.x), "r"(a.y), "r"(a.z), "r"(a.w), "r"(b.x), "r"(b.y));
}
__device__ __forceinline__ void mma16(float d[4], const uint4& a, const uint2& b) {
    asm("mma.sync.aligned.m16n8k16.row.col.f32.bf16.bf16.f32 "
        "{%0,%1,%2,%3},{%4,%5,%6,%7},{%8,%9},{%0,%1,%2,%3};"
        : "+f"(d[0]), "+f"(d[1]), "+f"(d[2]), "+f"(d[3])
        : "r"(a.x), "r"(a.y), "r"(a.z), "r"(a.w), "r"(b.x), "r"(b.y));
}

// tf32 frag indexers (k8 granularity)
__device__ __forceinline__ int AIDX(int mt, int k8, int r8, int cx) {
    return ((((mt << 1) + k8) << 3) + r8) * 4 + cx;
}
__device__ __forceinline__ int BIDX(int nt, int k8, int n8, int c) {
    return ((((nt << 1) + k8) << 3) + n8) * 4 + c;
}
// bf16 frag indexers (k16 granularity)
__device__ __forceinline__ int AIDXb(int mt, int r8, int cx) {
    return ((mt << 3) + r8) * 4 + cx;
}
__device__ __forceinline__ int BIDXb(int nt, int n8, int c) {
    return ((nt << 3) + n8) * 4 + c;
}

__device__ __forceinline__ void ldrow(const float* __restrict__ p, float e[8]) {
    float4 a = *(const float4*)p;
    float4 b = *(const float4*)(p + 4);
    e[0]=a.x; e[1]=a.y; e[2]=a.z; e[3]=a.w;
    e[4]=b.x; e[5]=b.y; e[6]=b.z; e[7]=b.w;
}

__device__ __forceinline__ void bsplit(float e, unsigned short& h, unsigned short& l) {
    __nv_bfloat16 bh = __float2bfloat16(e);
    h = __bfloat16_as_ushort(bh);
    l = __bfloat16_as_ushort(__float2bfloat16(e - __bfloat162float(bh)));
}

// ---- bf16 packs (hi + lo) ----
__device__ __forceinline__ void packA16(const float e[8], uint4* Ah, uint4* Al, int tid)
{
    const int lr = tid >> 1, kh = tid & 1;
    const int mt = lr >> 4, rr = lr & 15, r8 = rr & 7, rh = rr >> 3;
    const int comp = rh + (kh << 1);
    #pragma unroll
    for (int c = 0; c < 4; ++c) {
        unsigned short h0, l0, h1, l1;
        bsplit(e[2*c],   h0, l0);
        bsplit(e[2*c+1], h1, l1);
        const int idx = AIDXb(mt, r8, c ^ (r8 & 3));
        ((unsigned*)&Ah[idx])[comp] = (unsigned)h0 | ((unsigned)h1 << 16);
        ((unsigned*)&Al[idx])[comp] = (unsigned)l0 | ((unsigned)l1 << 16);
    }
}
__device__ __forceinline__ void packB16(const float e[8], uint2* Bh, uint2* Bl, int tid)
{
    const int ln = tid >> 1, kh = tid & 1;
    const int nt = ln >> 3, n8 = ln & 7;
    #pragma unroll
    for (int c = 0; c < 4; ++c) {
        unsigned short h0, l0, h1, l1;
        bsplit(e[2*c],   h0, l0);
        bsplit(e[2*c+1], h1, l1);
        const int idx = BIDXb(nt, n8, c);
        ((unsigned*)&Bh[idx])[kh] = (unsigned)h0 | ((unsigned)h1 << 16);
        ((unsigned*)&Bl[idx])[kh] = (unsigned)l0 | ((unsigned)l1 << 16);
    }
}

// ---- tf32 packs (AV + out-proj) ----
__device__ __forceinline__ void packA32(const float e[8], uint4* Ah, int tid)
{
    const int lr = tid >> 1;
    const int mt = lr >> 4, rr = lr & 15, r8 = rr & 7, rh = rr >> 3, k8 = tid & 1;
    #pragma unroll
    for (int j = 0; j < 8; ++j) {
        const int c = j & 3, ch = (j >> 2) & 1;
        const int comp = rh + (ch << 1);
        ((unsigned*)&Ah[AIDX(mt, k8, r8, c ^ (r8 & 3))])[comp] = f2tf32(e[j]);
    }
}
__device__ __forceinline__ unsigned f2u(float f) {
    unsigned b = __float_as_uint(f);
    return (b & 0x80000000u) ? ~b : (b | 0x80000000u);
}
__device__ __forceinline__ float u2f(unsigned u) {
    unsigned b = (u & 0x80000000u) ? (u & 0x7FFFFFFFu) : ~u;
    return __uint_as_float(b);
}
__device__ __forceinline__ void packA_av(const float e[8], uint4* Ah, int tid,
                                         unsigned kthbits, float m, float thr,
                                         float& psum)
{
    const int lr = tid >> 1;
    const int mt = lr >> 4, rr = lr & 15, r8 = rr & 7, rh = rr >> 3, k8 = tid & 1;
    #pragma unroll
    for (int j = 0; j < 8; ++j) {
        const bool keep = ((f2u(e[j]) & 0xFFFF0000u) >= kthbits) && (e[j] >= thr);
        const float pe = keep ? __expf(e[j] - m) : 0.f;
        psum += pe;
        const int c = j & 3, ch = (j >> 2) & 1;
        const int comp = rh + (ch << 1);
        ((unsigned*)&Ah[AIDX(mt, k8, r8, c ^ (r8 & 3))])[comp] = f2tf32(pe);
    }
}
__device__ __forceinline__ void packB32_nt(const float e[8], uint2* Bh, int tid)
{
    const int ln = tid >> 1;
    const int nt = ln >> 3, n8 = ln & 7, k8 = tid & 1;
    #pragma unroll
    for (int j = 0; j < 8; ++j) {
        const int c = j & 3, ph = (j >> 2) & 1;
        ((unsigned*)&Bh[BIDX(nt, k8, n8, c)])[ph] = f2tf32(e[j]);
    }
}
__device__ __forceinline__ void packB32_nn(const float e[4], uint2* Bh, int tid)
{
    const int kr = tid >> 4, nc = (tid & 15) << 2;
    const int k8 = kr >> 3, c = kr & 3, ph = (kr >> 2) & 1;
    #pragma unroll
    for (int j = 0; j < 4; ++j) {
        const int n = nc + j;
        ((unsigned*)&Bh[BIDX(n >> 3, k8, n & 7, c)])[ph] = f2tf32(e[j]);
    }
}

// ---------------------------------------------------------------------------
// QKV projections (bf16x3, pipelined) -> Q/K/V in [bh, s, d]
// ---------------------------------------------------------------------------
__global__ void __launch_bounds__(256, 2)
qkv_gemm_kernel(const float* __restrict__ x,
                const float* __restrict__ Wq,
                const float* __restrict__ Wk,
                const float* __restrict__ Wv)
{
    __shared__ uint4 Ah[2][256], Al[2][256];
    __shared__ uint2 Bh[2][512], Bl[2][512];

    const float* W = (blockIdx.z == 0) ? Wq : (blockIdx.z == 1 ? Wk : Wv);
    float*       C = (blockIdx.z == 0) ? g_Q : (blockIdx.z == 1 ? g_K : g_V);

    const int tid = threadIdx.x, lane = tid & 31, wid = tid >> 5;
    const int wm = wid >> 1, wn = wid & 1;
    const int row0 = blockIdx.y * 128, col0 = blockIdx.x * 128;
    const int r8 = lane >> 2, cc = lane & 3, cx = cc ^ (r8 & 3);
    const int lr = tid >> 1, lk = (tid & 1) << 3;

    const float* Ab = x + (size_t)(row0 + lr) * HIDDEN + lk;
    const float* Bb = W + (size_t)(col0 + lr) * HIDDEN + lk;

    float ea[8], eb[8];
    ldrow(Ab, ea); ldrow(Bb, eb);
    packA16(ea, Ah[0], Al[0], tid);
    packB16(eb, Bh[0], Bl[0], tid);
    __syncthreads();

    float d[2][8][4] = {};
    for (int k0 = 0; k0 < HIDDEN; k0 += 16) {
        const int cur = (k0 >> 4) & 1, nxt = cur ^ 1;
        const bool more = (k0 + 16) < HIDDEN;
        if (more) { ldrow(Ab + k0 + 16, ea); ldrow(Bb + k0 + 16, eb); }

        uint4 ah[2], al[2];
        #pragma unroll
        for (int mt = 0; mt < 2; ++mt) {
            ah[mt] = Ah[cur][AIDXb(wm * 2 + mt, r8, cx)];
            al[mt] = Al[cur][AIDXb(wm * 2 + mt, r8, cx)];
        }
        #pragma unroll
        for (int nt = 0; nt < 8; ++nt) {
            const int bi = BIDXb(wn * 8 + nt, r8, cc);
            const uint2 bhv = Bh[cur][bi], blv = Bl[cur][bi];
            #pragma unroll
            for (int mt = 0; mt < 2; ++mt) {
                mma16(d[mt][nt], ah[mt], bhv);
                mma16(d[mt][nt], ah[mt], blv);
                mma16(d[mt][nt], al[mt], bhv);
            }
        }
        if (more) {
            packA16(ea, Ah[nxt], Al[nxt], tid);
            packB16(eb, Bh[nxt], Bl[nxt], tid);
        }
        __syncthreads();
    }

    const int g = lane >> 2, t2 = (lane & 3) << 1;
    #pragma unroll
    for (int mt = 0; mt < 2; ++mt) {
        const int rA = row0 + (wm * 2 + mt) * 16 + g;
        const int rB = rA + 8;
        const int bA = rA >> 11, sA = rA & (SEQ - 1);
        const int bB = rB >> 11, sB = rB & (SEQ - 1);
        #pragma unroll
        for (int nt = 0; nt < 8; ++nt) {
            const int col = col0 + (wn * 8 + nt) * 8 + t2;
            const int h = col >> 6, dd = col & 63;
            *(float2*)&C[(((size_t)(bA * HEADS + h) * SEQ) + sA) * HEAD_DIM + dd] =
                make_float2(d[mt][nt][0], d[mt][nt][1]);
            *(float2*)&C[(((size_t)(bB * HEADS + h) * SEQ) + sB) * HEAD_DIM + dd] =
                make_float2(d[mt][nt][2], d[mt][nt][3]);
        }
    }
}

// ---------------------------------------------------------------------------
// Scores (bf16x3, pipelined): writes fp32 S and u16 orderable keys
// ---------------------------------------------------------------------------
__global__ void __launch_bounds__(256, 2)
scores_gemm_kernel()
{
    __shared__ uint4 Ah[2][256], Al[2][256];
    __shared__ uint2 Bh[2][512], Bl[2][512];

    const int bh = blockIdx.z;
    const float* Qb = g_Q + (size_t)bh * SEQ * HEAD_DIM;
    const float* Kb = g_K + (size_t)bh * SEQ * HEAD_DIM;
    float*       Sb = g_S + (size_t)bh * SEQ * SEQ;
    unsigned*    Kw = g_key16 + (size_t)bh * SEQ * (SEQ / 2);

    const int tid = threadIdx.x, lane = tid & 31, wid = tid >> 5;
    const int wm = wid >> 1, wn = wid & 1;
    const int row0 = blockIdx.y * 128, col0 = blockIdx.x * 128;
    const int r8 = lane >> 2, cc = lane & 3, cx = cc ^ (r8 & 3);
    const int lr = tid >> 1, lk = (tid & 1) << 3;

    const float* Ab = Qb + (size_t)(row0 + lr) * HEAD_DIM + lk;
    const float* Bb = Kb + (size_t)(col0 + lr) * HEAD_DIM + lk;

    float ea[8], eb[8];
    ldrow(Ab, ea); ldrow(Bb, eb);
    packA16(ea, Ah[0], Al[0], tid);
    packB16(eb, Bh[0], Bl[0], tid);
    __syncthreads();

    float d[2][8][4] = {};
    #pragma unroll
    for (int k0 = 0; k0 < HEAD_DIM; k0 += 16) {
        const int cur = (k0 >> 4) & 1, nxt = cur ^ 1;
        const bool more = (k0 + 16) < HEAD_DIM;
        if (more) { ldrow(Ab + k0 + 16, ea); ldrow(Bb + k0 + 16, eb); }

        uint4 ah[2], al[2];
        #pragma unroll
        for (int mt = 0; mt < 2; ++mt) {
            ah[mt] = Ah[cur][AIDXb(wm * 2 + mt, r8, cx)];
            al[mt] = Al[cur][AIDXb(wm * 2 + mt, r8, cx)];
        }
        #pragma unroll
        for (int nt = 0; nt < 8; ++nt) {
            const int bi = BIDXb(wn * 8 + nt, r8, cc);
            const uint2 bhv = Bh[cur][bi], blv = Bl[cur][bi];
            #pragma unroll
            for (int mt = 0; mt < 2; ++mt) {
                mma16(d[mt][nt], ah[mt], bhv);
                mma16(d[mt][nt], ah[mt], blv);
                mma16(d[mt][nt], al[mt], bhv);
            }
        }
        if (more) {
            packA16(ea, Ah[nxt], Al[nxt], tid);
            packB16(eb, Bh[nxt], Bl[nxt], tid);
        }
        __syncthreads();
    }

    const int g = lane >> 2, t2 = (lane & 3) << 1;
    #pragma unroll
    for (int mt = 0; mt < 2; ++mt) {
        const int qA = row0 + (wm * 2 + mt) * 16 + g;
        const int qB = qA + 8;
        #pragma unroll
        for (int nt = 0; nt < 8; ++nt) {
            const int col = col0 + (wn * 8 + nt) * 8 + t2;
            const float a0 = d[mt][nt][0] * 0.125f, a1 = d[mt][nt][1] * 0.125f;
            const float b0 = d[mt][nt][2] * 0.125f, b1 = d[mt][nt][3] * 0.125f;
            *(float2*)&Sb[(size_t)qA * SEQ + col] = make_float2(a0, a1);
            *(float2*)&Sb[(size_t)qB * SEQ + col] = make_float2(b0, b1);
            Kw[((size_t)qA * SEQ + col) >> 1] = (f2u(a0) >> 16) | ((f2u(a1) >> 16) << 16);
            Kw[((size_t)qB * SEQ + col) >> 1] = (f2u(b0) >> 16) | ((f2u(b1) >> 16) << 16);
        }
    }
}

// ---------------------------------------------------------------------------
// select16: per-row 2-pass radix on u16 keys -> (kthbits, m~)
// ---------------------------------------------------------------------------
__global__ void select16_kernel()
{
    const int tid = threadIdx.x;
    const unsigned* Krow = g_key16 + (size_t)blockIdx.x * (SEQ / 2);

    __shared__ unsigned hist[256];
    __shared__ unsigned wsum[8];
    __shared__ unsigned s_b;
    __shared__ int      s_kk;
    __shared__ unsigned s_max;

    uint4 kv = ((const uint4*)Krow)[tid];   // 8 u16 keys
    unsigned k[8] = { kv.x & 0xFFFFu, kv.x >> 16, kv.y & 0xFFFFu, kv.y >> 16,
                      kv.z & 0xFFFFu, kv.z >> 16, kv.w & 0xFFFFu, kv.w >> 16 };

    const int lane = tid & 31, wrp = tid >> 5;

    // ---- row max key ----
    unsigned mk = k[0];
    #pragma unroll
    for (int t = 1; t < 8; ++t) mk = max(mk, k[t]);
    #pragma unroll
    for (int o = 16; o > 0; o >>= 1) mk = max(mk, __shfl_xor_sync(0xFFFFFFFFu, mk, o));
    if (lane == 0) wsum[wrp] = mk;
    __syncthreads();
    if (tid == 0) {
        unsigned m0 = wsum[0];
        #pragma unroll
        for (int w = 1; w < 8; ++w) m0 = max(m0, wsum[w]);
        s_max = m0;
    }
    __syncthreads();
    const unsigned maxk = s_max;

    // ---- pass 1 (high byte) ----
    int kk = KKEEP;
    unsigned b1;
    hist[tid] = 0;
    __syncthreads();
    #pragma unroll
    for (int t = 0; t < 8; ++t) {
        const unsigned bin = k[t] >> 8;
        const unsigned peers = __match_any_sync(0xFFFFFFFFu, bin);
        if (lane == (__ffs(peers) - 1))
            atomicAdd(&hist[bin], (unsigned)__popc(peers));
    }
    __syncthreads();
    {
        unsigned myc = hist[tid];
        unsigned cum = myc;
        #pragma unroll
        for (int o = 1; o < 32; o <<= 1) {
            unsigned g2 = __shfl_down_sync(0xFFFFFFFFu, cum, o);
            if (lane + o < 32) cum += g2;
        }
        if (lane == 0) wsum[wrp] = cum;
        __syncthreads();
        unsigned above = 0;
        #pragma unroll
        for (int w = 0; w < 8; ++w) if (w > wrp) above += wsum[w];
        cum += above;
        if (cum >= (unsigned)kk && (cum - myc) < (unsigned)kk) {
            s_b  = (unsigned)tid;
            s_kk = kk - (int)(cum - myc);
        }
    }
    __syncthreads();
    b1 = s_b;
    kk = s_kk;
    __syncthreads();

    // ---- pass 2 (low byte, among prefix matches) ----
    hist[tid] = 0;
    __syncthreads();
    #pragma unroll
    for (int t = 0; t < 8; ++t) {
        const bool ok = (k[t] >> 8) == b1;
        const unsigned mok = __ballot_sync(0xFFFFFFFFu, ok);
        if (mok) {
            const unsigned bin = k[t] & 0xFFu;
            const unsigned key = ok ? bin : (256u + (unsigned)lane);
            const unsigned peers = __match_any_sync(0xFFFFFFFFu, key);
            if (ok && lane == (__ffs(peers) - 1))
                atomicAdd(&hist[bin], (unsigned)__popc(peers));
        }
    }
    __syncthreads();
    {
        unsigned myc = hist[tid];
        unsigned cum = myc;
        #pragma unroll
        for (int o = 1; o < 32; o <<= 1) {
            unsigned g2 = __shfl_down_sync(0xFFFFFFFFu, cum, o);
            if (lane + o < 32) cum += g2;
        }
        if (lane == 0) wsum[wrp] = cum;
        __syncthreads();
        unsigned above = 0;
        #pragma unroll
        for (int w = 0; w < 8; ++w) if (w > wrp) above += wsum[w];
        cum += above;
        if (cum >= (unsigned)kk && (cum - myc) < (unsigned)kk)
            s_b = (b1 << 8) | (unsigned)tid;
    }
    __syncthreads();

    if (tid == 0) {
        const unsigned kth16 = s_b;
        g_par[blockIdx.x] = make_float4(__uint_as_float(kth16 << 16),
                                        u2f(maxk << 16), 0.f, 0.f);
    }
}

// ---------------------------------------------------------------------------
// AV (tf32 x1, fused gate+softmax+sum, pipelined)
// ---------------------------------------------------------------------------
__global__ void __launch_bounds__(256, 2)
av_gemm_kernel(const float* __restrict__ thr_ptr)
{
    __shared__ uint4 Ah[2][512];
    __shared__ uint2 Bh[2][512];
    __shared__ float rowsum[128];

    const int bh   = blockIdx.y;
    const int row0 = blockIdx.x * 128;
    const float* Sb = g_S + (size_t)bh * SEQ * SEQ;
    const float* Vb = g_V + (size_t)bh * SEQ * HEAD_DIM;

    const int tid = threadIdx.x, lane = tid & 31, wid = tid >> 5;
    const int wm = wid >> 1, wn = wid & 1;
    const int r8 = lane >> 2, cc = lane & 3, cx = cc ^ (r8 & 3);
    const int lr = tid >> 1, lk = (tid & 1) << 3;
    const int kr = tid >> 4, nc = (tid & 15) << 2;

    const float4 par = g_par[(size_t)bh * SEQ + row0 + lr];
    const unsigned kthbits = __float_as_uint(par.x);
    const float mrow = par.y;
    const float thr  = fminf(fmaxf(*thr_ptr, 0.f), 1.f);

    const float* Ab = Sb + (size_t)(row0 + lr) * SEQ + lk;
    const float* Bb = Vb + (size_t)kr * HEAD_DIM + nc;

    float psum = 0.f;
    float ea[8], evb[4];
    ldrow(Ab, ea);
    { float4 v = *(const float4*)Bb; evb[0]=v.x; evb[1]=v.y; evb[2]=v.z; evb[3]=v.w; }
    packA_av(ea, Ah[0], tid, kthbits, mrow, thr, psum);
    packB32_nn(evb, Bh[0], tid);
    __syncthreads();

    float d[2][4][4] = {};
    for (int k0 = 0; k0 < SEQ; k0 += 16) {
        const int cur = (k0 >> 4) & 1, nxt = cur ^ 1;
        const bool more = (k0 + 16) < SEQ;
        if (more) {
            ldrow(Ab + k0 + 16, ea);
            float4 v = *(const float4*)(Bb + (size_t)(k0 + 16) * HEAD_DIM);
            evb[0]=v.x; evb[1]=v.y; evb[2]=v.z; evb[3]=v.w;
        }

        #pragma unroll
        for (int k8 = 0; k8 < 2; ++k8) {
            uint4 ah[2];
            #pragma unroll
            for (int mt = 0; mt < 2; ++mt)
                ah[mt] = Ah[cur][AIDX(wm * 2 + mt, k8, r8, cx)];
            #pragma unroll
            for (int nt = 0; nt < 4; ++nt) {
                const uint2 bv = Bh[cur][BIDX(wn * 4 + nt, k8, r8, cc)];
                #pragma unroll
                for (int mt = 0; mt < 2; ++mt)
                    mma8(d[mt][nt], ah[mt], bv);
            }
        }
        if (more) {
            packA_av(ea, Ah[nxt], tid, kthbits, mrow, thr, psum);
            packB32_nn(evb, Bh[nxt], tid);
        }
        __syncthreads();
    }

    // row sums -> inverse
    {
        const float tot = psum + __shfl_xor_sync(0xFFFFFFFFu, psum, 1);
        if ((tid & 1) == 0) rowsum[lr] = tot;
    }
    __syncthreads();

    const int b = bh >> 4, h = bh & 15;
    const int g = lane >> 2, t2 = (lane & 3) << 1;
    #pragma unroll
    for (int mt = 0; mt < 2; ++mt) {
        const int qA = row0 + (wm * 2 + mt) * 16 + g;
        const int qB = qA + 8;
        const float invA = 1.f / rowsum[qA - row0];
        const float invB = 1.f / rowsum[qB - row0];
        #pragma unroll
        for (int nt = 0; nt < 4; ++nt) {
            const int col = (wn * 4 + nt) * 8 + t2;
            *(float2*)&g_O[(((size_t)b * SEQ + qA) * HIDDEN) + h * HEAD_DIM + col] =
                make_float2(d[mt][nt][0] * invA, d[mt][nt][1] * invA);
            *(float2*)&g_O[(((size_t)b * SEQ + qB) * HIDDEN) + h * HEAD_DIM + col] =
                make_float2(d[mt][nt][2] * invB, d[mt][nt][3] * invB);
        }
    }
}

// ---------------------------------------------------------------------------
// Output projection (tf32 x1, pipelined): Y = g_O @ Wo^T + bo
// ---------------------------------------------------------------------------
__global__ void __launch_bounds__(256, 2)
out_gemm_kernel(const float* __restrict__ Wo,
                const float* __restrict__ bo,
                float* __restrict__ Y)
{
    __shared__ uint4 Ah[2][512];
    __shared__ uint2 Bh[2][1024];

    const int tid = threadIdx.x, lane = tid & 31, wid = tid >> 5;
    const int wm = wid >> 1, wn = wid & 1;
    const int row0 = blockIdx.y * 128, col0 = blockIdx.x * 128;
    const int r8 = lane >> 2, cc = lane & 3, cx = cc ^ (r8 & 3);
    const int lr = tid >> 1, lk = (tid & 1) << 3;

    const float* Ab = g_O + (size_t)(row0 + lr) * HIDDEN + lk;
    const float* Bb = Wo  + (size_t)(col0 + lr) * HIDDEN + lk;

    float ea[8], eb[8];
    ldrow(Ab, ea); ldrow(Bb, eb);
    packA32(ea, Ah[0], tid);
    packB32_nt(eb, Bh[0], tid);
    __syncthreads();

    float d[2][8][4] = {};
    for (int k0 = 0; k0 < HIDDEN; k0 += 16) {
        const int cur = (k0 >> 4) & 1, nxt = cur ^ 1;
        const bool more = (k0 + 16) < HIDDEN;
        if (more) { ldrow(Ab + k0 + 16, ea); ldrow(Bb + k0 + 16, eb); }

        #pragma unroll
        for (int k8 = 0; k8 < 2; ++k8) {
            uint4 ah[2];
            #pragma unroll
            for (int mt = 0; mt < 2; ++mt)
                ah[mt] = Ah[cur][AIDX(wm * 2 + mt, k8, r8, cx)];
            #pragma unroll
            for (int nt = 0; nt < 8; ++nt) {
                const uint2 bv = Bh[cur][BIDX(wn * 8 + nt, k8, r8, cc)];
                #pragma unroll
                for (int mt = 0; mt < 2; ++mt)
                    mma8(d[mt][nt], ah[mt], bv);
            }
        }
        if (more) {
            packA32(ea, Ah[nxt], tid);
            packB32_nt(eb, Bh[nxt], tid);
        }
        __syncthreads();
    }

    const int g = lane >> 2, t2 = (lane & 3) << 1;
    #pragma unroll
    for (int mt = 0; mt < 2; ++mt) {
        const int rA = row0 + (wm * 2 + mt) * 16 + g;
        const int rB = rA + 8;
        #pragma unroll
        for (int nt = 0; nt < 8; ++nt) {
            const int col = col0 + (wn * 8 + nt) * 8 + t2;
            const float b0 = bo[col], b1 = bo[col + 1];
            *(float2*)&Y[(size_t)rA * HIDDEN + col] =
                make_float2(d[mt][nt][0] + b0, d[mt][nt][1] + b1);
            *(float2*)&Y[(size_t)rB * HIDDEN + col] =
                make_float2(d[mt][nt][2] + b0, d[mt][nt][3] + b1);
        }
    }
}

// ---------------------------------------------------------------------------
extern "C" void kernel_launch(void* const* d_in, const int* in_sizes, int n_in,
                              void* d_out, int out_size)
{
    const float* x   = (const float*)d_in[0];
    const float* Wq  = (const float*)d_in[1];
    const float* Wk  = (const float*)d_in[2];
    const float* Wv  = (const float*)d_in[3];
    const float* Wo  = (const float*)d_in[4];
    const float* bo  = (const float*)d_in[5];
    const float* thr = (const float*)d_in[6];
    float* out = (float*)d_out;

    dim3 gqkv(HIDDEN / 128, MROWS / 128, 3);
    qkv_gemm_kernel<<<gqkv, 256>>>(x, Wq, Wk, Wv);

    dim3 gs(SEQ / 128, SEQ / 128, BH);
    scores_gemm_kernel<<<gs, 256>>>();

    select16_kernel<<<BH * SEQ, 256>>>();

    dim3 gav(SEQ / 128, BH);
    av_gemm_kernel<<<gav, 256>>>(thr);

    dim3 go(HIDDEN / 128, MROWS / 128);
    out_gemm_kernel<<<go, 256>>>(Wo, bo, out);
}